// round 1
// baseline (speedup 1.0000x reference)
#include <cuda_runtime.h>
#include <cuda_bf16.h>
#include <math.h>

#define N_NODES 8192
#define F_IN    256
#define F_OUT   128
#define LRELU_ALPHA 0.2f

// Scratch (allocation-free rule: __device__ globals)
__device__ float g_Wh[N_NODES * F_OUT];   // 4 MB
__device__ float g_Wh1[N_NODES];
__device__ float g_Wh2[N_NODES];

typedef unsigned long long u64t;

__device__ __forceinline__ u64t pack2(float x) {
    u64t r; asm("mov.b64 %0, {%1, %1};" : "=l"(r) : "f"(x)); return r;
}
__device__ __forceinline__ void ffma2(u64t& d, u64t a, u64t b) {
    asm("fma.rn.f32x2 %0, %1, %2, %0;" : "+l"(d) : "l"(a), "l"(b));
}
__device__ __forceinline__ float2 unpack2(u64t v) {
    float2 f; asm("mov.b64 {%0, %1}, %2;" : "=f"(f.x), "=f"(f.y) : "l"(v)); return f;
}

// ---------------------------------------------------------------------------
// Kernel A: Wh = h @ W   (8192x256 @ 256x128), 128 blocks x 256 threads,
// each block produces a 64x128 output tile. k-tiles of 64.
// ---------------------------------------------------------------------------
__global__ __launch_bounds__(256) void gemm_wh(const float* __restrict__ h,
                                               const float* __restrict__ W) {
    __shared__ __align__(16) float h_s[64][64];   // [k][i] (XOR-rotated columns)
    __shared__ __align__(16) float W_s[64][F_OUT];

    const int t    = threadIdx.x;
    const int lane = t & 31;
    const int wid  = t >> 5;           // 8 warps
    const int ib   = wid * 8;          // warp's 8 output rows within tile
    const int i0   = blockIdx.x * 64;
    const int tx   = t & 63;           // k within tile
    const int ty   = t >> 6;           // 0..3

    float acc[8][4] = {};

    for (int k0 = 0; k0 < F_IN; k0 += 64) {
        // h tile, stored transposed [k][i] with per-row rotation (conflict-free)
        #pragma unroll
        for (int r = 0; r < 16; r++) {
            int i = ty * 16 + r;
            h_s[tx][(i + tx) & 63] = h[(size_t)(i0 + i) * F_IN + k0 + tx];
        }
        // W tile (full contiguous rows)
        {
            const float4* Wg = reinterpret_cast<const float4*>(W + (size_t)k0 * F_OUT);
            float4* Ws4 = reinterpret_cast<float4*>(&W_s[0][0]);
            #pragma unroll
            for (int r = 0; r < 8; r++) Ws4[t + r * 256] = Wg[t + r * 256];
        }
        __syncthreads();

        #pragma unroll 8
        for (int k = 0; k < 64; k++) {
            float4 wv = reinterpret_cast<float4*>(&W_s[k][0])[lane];
            #pragma unroll
            for (int r = 0; r < 8; r++) {
                float hv = h_s[k][(ib + r + k) & 63];   // broadcast
                acc[r][0] += hv * wv.x;
                acc[r][1] += hv * wv.y;
                acc[r][2] += hv * wv.z;
                acc[r][3] += hv * wv.w;
            }
        }
        __syncthreads();
    }

    #pragma unroll
    for (int r = 0; r < 8; r++) {
        int i = i0 + ib + r;
        float4 v = make_float4(acc[r][0], acc[r][1], acc[r][2], acc[r][3]);
        reinterpret_cast<float4*>(&g_Wh[(size_t)i * F_OUT])[lane] = v;
    }
}

// ---------------------------------------------------------------------------
// Kernel A2: Wh1[i] = Wh[i,:].a[:128],  Wh2[i] = Wh[i,:].a[128:]
// one warp per row; 1024 blocks x 256 threads
// ---------------------------------------------------------------------------
__global__ __launch_bounds__(256) void attn_coeffs(const float* __restrict__ a) {
    const int t    = threadIdx.x;
    const int lane = t & 31;
    const int wid  = t >> 5;
    const int i    = blockIdx.x * 8 + wid;

    float4 wh = reinterpret_cast<const float4*>(&g_Wh[(size_t)i * F_OUT])[lane];
    float4 a1 = reinterpret_cast<const float4*>(a)[lane];
    float4 a2 = reinterpret_cast<const float4*>(a + F_OUT)[lane];

    float s1 = wh.x * a1.x + wh.y * a1.y + wh.z * a1.z + wh.w * a1.w;
    float s2 = wh.x * a2.x + wh.y * a2.y + wh.z * a2.z + wh.w * a2.w;
    #pragma unroll
    for (int o = 16; o > 0; o >>= 1) {
        s1 += __shfl_xor_sync(0xFFFFFFFFu, s1, o);
        s2 += __shfl_xor_sync(0xFFFFFFFFu, s2, o);
    }
    if (lane == 0) { g_Wh1[i] = s1; g_Wh2[i] = s2; }
}

// ---------------------------------------------------------------------------
// Kernel B: fused masked-softmax aggregation.
// out[i,:] = elu( (sum_j w_ij * Wh[j,:]) / (sum_j w_ij) )
// w_ij = adj[i,j] ? exp(leakyrelu(Wh1[i] + Wh2[j])) : 0   (no max-subtraction:
// scores ~N(0,1), exp can't overflow; identical result after normalization)
// 128 blocks (64 rows each) x 256 threads; j-tiles of 64.
// ---------------------------------------------------------------------------
__global__ __launch_bounds__(256) void aggregate(const int* __restrict__ adj,
                                                 float* __restrict__ out) {
    __shared__ __align__(16) float Wh_s[64][F_OUT];  // 32 KB
    __shared__ __align__(16) float w_s[64][64];      // 16 KB, [i][j]

    const int t    = threadIdx.x;
    const int lane = t & 31;
    const int wid  = t >> 5;          // 8 warps
    const int ib   = wid * 8;         // warp's 8 rows within tile
    const int i0   = blockIdx.x * 64;
    const int tx   = t & 63;          // j within tile (stage 1)
    const int ty   = t >> 6;          // 0..3

    // stage-1 per-thread row scores (fixed i's for this thread, hoisted)
    float wh1r[16];
    #pragma unroll
    for (int r = 0; r < 16; r++) wh1r[r] = g_Wh1[i0 + ty * 16 + r];

    u64t acc2[8][2] = {};             // packed f32x2 accumulators: 8 rows x 4 feats
    float denom = 0.0f;               // valid for t < 64 (row t of tile)

    for (int j0 = 0; j0 < N_NODES; j0 += 64) {
        // ---- load Wh tile (64 x 128 floats) ----
        {
            const float4* Wg = reinterpret_cast<const float4*>(g_Wh + (size_t)j0 * F_OUT);
            float4* Ws4 = reinterpret_cast<float4*>(&Wh_s[0][0]);
            #pragma unroll
            for (int r = 0; r < 8; r++) Ws4[t + r * 256] = Wg[t + r * 256];
        }
        // ---- stage 1: compute w tile ----
        {
            const float wh2 = g_Wh2[j0 + tx];
            #pragma unroll
            for (int r = 0; r < 16; r++) {
                int i = ty * 16 + r;
                int av = adj[(size_t)(i0 + i) * N_NODES + j0 + tx];
                float s = wh1r[r] + wh2;
                s = (s > 0.0f) ? s : LRELU_ALPHA * s;
                float w = (av > 0) ? __expf(s) : 0.0f;
                w_s[i][tx] = w;       // lanes: j consecutive -> conflict-free
            }
        }
        __syncthreads();

        // ---- per-tile denominator: thread t (<64) sums row t, bank-rotated ----
        if (t < 64) {
            float d = 0.0f;
            #pragma unroll
            for (int j = 0; j < 64; j++) d += w_s[t][(j + t) & 63];
            denom += d;
        }

        // ---- stage 2: acc += w * Wh  (packed f32x2 FMAs) ----
        #pragma unroll 8
        for (int j = 0; j < 64; j++) {
            ulonglong2 wh = reinterpret_cast<const ulonglong2*>(&Wh_s[j][0])[lane];
            #pragma unroll
            for (int r = 0; r < 8; r++) {
                u64t wr = pack2(w_s[ib + r][j]);   // broadcast read
                ffma2(acc2[r][0], wr, wh.x);
                ffma2(acc2[r][1], wr, wh.y);
            }
        }
        __syncthreads();
    }

    // publish denominators (reuse w_s row 0)
    if (t < 64) w_s[0][t] = denom;
    __syncthreads();

    // epilogue: normalize + ELU, write out
    #pragma unroll
    for (int r = 0; r < 8; r++) {
        float inv = 1.0f / w_s[0][ib + r];
        float2 lo = unpack2(acc2[r][0]);
        float2 hi = unpack2(acc2[r][1]);
        float v[4] = { lo.x * inv, lo.y * inv, hi.x * inv, hi.y * inv };
        #pragma unroll
        for (int c = 0; c < 4; c++)
            v[c] = (v[c] > 0.0f) ? v[c] : expm1f(v[c]);
        int i = i0 + ib + r;
        reinterpret_cast<float4*>(&out[(size_t)i * F_OUT])[lane] =
            make_float4(v[0], v[1], v[2], v[3]);
    }
}

// ---------------------------------------------------------------------------
extern "C" void kernel_launch(void* const* d_in, const int* in_sizes, int n_in,
                              void* d_out, int out_size) {
    const float* h   = (const float*)d_in[0];
    const int*   adj = (const int*)d_in[1];
    const float* W   = (const float*)d_in[2];
    const float* a   = (const float*)d_in[3];
    float* out = (float*)d_out;

    gemm_wh<<<N_NODES / 64, 256>>>(h, W);
    attn_coeffs<<<N_NODES / 8, 256>>>(a);
    aggregate<<<N_NODES / 64, 256>>>(adj, out);
}

// round 2
// speedup vs baseline: 1.5499x; 1.5499x over previous
#include <cuda_runtime.h>
#include <cuda_bf16.h>
#include <math.h>

#define N_NODES 8192
#define F_IN    256
#define F_OUT   128
#define LRELU_ALPHA 0.2f
#define JSPLIT  4
#define JCHUNK  (N_NODES / JSPLIT)   // 2048

// Scratch (allocation-free rule: __device__ globals)
__device__ float g_Wh[N_NODES * F_OUT];                 // 4 MB
__device__ float g_Wh1[N_NODES];
__device__ float g_Wh2[N_NODES];
__device__ float g_pnum[JSPLIT][N_NODES][F_OUT];        // 16 MB partial numerators
__device__ float g_pden[JSPLIT][N_NODES];               // partial denominators

typedef unsigned long long u64t;

__device__ __forceinline__ u64t pack2(float x) {
    u64t r; asm("mov.b64 %0, {%1, %1};" : "=l"(r) : "f"(x)); return r;
}
__device__ __forceinline__ void ffma2(u64t& d, u64t a, u64t b) {
    asm("fma.rn.f32x2 %0, %1, %2, %0;" : "+l"(d) : "l"(a), "l"(b));
}
__device__ __forceinline__ float2 unpack2(u64t v) {
    float2 f; asm("mov.b64 {%0, %1}, %2;" : "=f"(f.x), "=f"(f.y) : "l"(v)); return f;
}

// ---------------------------------------------------------------------------
// Kernel A: Wh = h @ W   (8192x256 @ 256x128), 128 blocks x 256 threads.
// ---------------------------------------------------------------------------
__global__ __launch_bounds__(256) void gemm_wh(const float* __restrict__ h,
                                               const float* __restrict__ W) {
    __shared__ __align__(16) float h_s[64][64];   // [k][i] (XOR-rotated columns)
    __shared__ __align__(16) float W_s[64][F_OUT];

    const int t    = threadIdx.x;
    const int lane = t & 31;
    const int wid  = t >> 5;
    const int ib   = wid * 8;
    const int i0   = blockIdx.x * 64;
    const int tx   = t & 63;
    const int ty   = t >> 6;

    float acc[8][4] = {};

    for (int k0 = 0; k0 < F_IN; k0 += 64) {
        #pragma unroll
        for (int r = 0; r < 16; r++) {
            int i = ty * 16 + r;
            h_s[tx][(i + tx) & 63] = h[(size_t)(i0 + i) * F_IN + k0 + tx];
        }
        {
            const float4* Wg = reinterpret_cast<const float4*>(W + (size_t)k0 * F_OUT);
            float4* Ws4 = reinterpret_cast<float4*>(&W_s[0][0]);
            #pragma unroll
            for (int r = 0; r < 8; r++) Ws4[t + r * 256] = Wg[t + r * 256];
        }
        __syncthreads();

        #pragma unroll 8
        for (int k = 0; k < 64; k++) {
            float4 wv = reinterpret_cast<float4*>(&W_s[k][0])[lane];
            #pragma unroll
            for (int r = 0; r < 8; r++) {
                float hv = h_s[k][(ib + r + k) & 63];
                acc[r][0] += hv * wv.x;
                acc[r][1] += hv * wv.y;
                acc[r][2] += hv * wv.z;
                acc[r][3] += hv * wv.w;
            }
        }
        __syncthreads();
    }

    #pragma unroll
    for (int r = 0; r < 8; r++) {
        int i = i0 + ib + r;
        reinterpret_cast<float4*>(&g_Wh[(size_t)i * F_OUT])[lane] =
            make_float4(acc[r][0], acc[r][1], acc[r][2], acc[r][3]);
    }
}

// ---------------------------------------------------------------------------
// Kernel A2: Wh1[i] = Wh[i,:].a[:128],  Wh2[i] = Wh[i,:].a[128:]
// ---------------------------------------------------------------------------
__global__ __launch_bounds__(256) void attn_coeffs(const float* __restrict__ a) {
    const int t    = threadIdx.x;
    const int lane = t & 31;
    const int wid  = t >> 5;
    const int i    = blockIdx.x * 8 + wid;

    float4 wh = reinterpret_cast<const float4*>(&g_Wh[(size_t)i * F_OUT])[lane];
    float4 a1 = reinterpret_cast<const float4*>(a)[lane];
    float4 a2 = reinterpret_cast<const float4*>(a + F_OUT)[lane];

    float s1 = wh.x * a1.x + wh.y * a1.y + wh.z * a1.z + wh.w * a1.w;
    float s2 = wh.x * a2.x + wh.y * a2.y + wh.z * a2.z + wh.w * a2.w;
    #pragma unroll
    for (int o = 16; o > 0; o >>= 1) {
        s1 += __shfl_xor_sync(0xFFFFFFFFu, s1, o);
        s2 += __shfl_xor_sync(0xFFFFFFFFu, s2, o);
    }
    if (lane == 0) { g_Wh1[i] = s1; g_Wh2[i] = s2; }
}

// ---------------------------------------------------------------------------
// Kernel B: fused masked-softmax aggregation, j-split for occupancy.
// Block (bx, js): rows [bx*64, bx*64+64), cols [js*2048, js*2048+2048).
// Writes partial numerator / denominator; combine kernel finishes.
// w_ij = adj_ij ? exp(leakyrelu(Wh1_i + Wh2_j)) : 0 (no max-subtraction:
// scores ~N(0,1) over 64M samples, exp can't overflow; identical after norm).
// ---------------------------------------------------------------------------
__global__ __launch_bounds__(256, 3) void aggregate(const int* __restrict__ adj) {
    __shared__ __align__(16) float Wh_s[64][F_OUT];  // 32 KB
    __shared__ __align__(16) u64t  w2_s[64][64];     // 32 KB, {w,w} packed

    const int t    = threadIdx.x;
    const int lane = t & 31;
    const int wid  = t >> 5;          // 8 warps
    const int ib   = wid * 8;
    const int i0   = blockIdx.x * 64;
    const int js   = blockIdx.y;
    const int tx   = t & 63;          // j within tile (stage 1)
    const int ty   = t >> 6;          // 0..3

    u64t acc2[8][2] = {};
    float denom = 0.0f;               // valid for t < 64 (row t of tile)

    const int jbeg = js * JCHUNK;
    const int jend = jbeg + JCHUNK;

    for (int j0 = jbeg; j0 < jend; j0 += 64) {
        // ---- load Wh tile (64 x 128 floats) ----
        {
            const float4* Wg = reinterpret_cast<const float4*>(g_Wh + (size_t)j0 * F_OUT);
            float4* Ws4 = reinterpret_cast<float4*>(&Wh_s[0][0]);
            #pragma unroll
            for (int r = 0; r < 8; r++) Ws4[t + r * 256] = Wg[t + r * 256];
        }
        // ---- stage 1: compute w tile, pre-duplicated {w,w} ----
        {
            const float wh2 = g_Wh2[j0 + tx];
            #pragma unroll
            for (int r = 0; r < 16; r++) {
                int i = ty * 16 + r;
                int av = adj[(size_t)(i0 + i) * N_NODES + j0 + tx];
                float s = g_Wh1[i0 + i] + wh2;       // broadcast L1 hit
                s = (s > 0.0f) ? s : LRELU_ALPHA * s;
                float w = (av > 0) ? __expf(s) : 0.0f;
                w2_s[i][tx] = pack2(w);
            }
        }
        __syncthreads();

        // ---- per-tile denominator: thread t (<64) sums row t, rotated ----
        if (t < 64) {
            float d = 0.0f;
            #pragma unroll
            for (int j = 0; j < 64; j++) {
                float2 p = unpack2(w2_s[t][(j + t) & 63]);
                d += p.x;
            }
            denom += d;
        }

        // ---- stage 2: acc += w * Wh  (packed f32x2 FMAs, no pack movs) ----
        #pragma unroll 4
        for (int j = 0; j < 64; j++) {
            ulonglong2 wh = reinterpret_cast<const ulonglong2*>(&Wh_s[j][0])[lane];
            #pragma unroll
            for (int r = 0; r < 8; r++) {
                u64t wr = w2_s[ib + r][j];           // LDS.64 broadcast
                ffma2(acc2[r][0], wr, wh.x);
                ffma2(acc2[r][1], wr, wh.y);
            }
        }
        __syncthreads();
    }

    if (t < 64) g_pden[js][i0 + t] = denom;

    #pragma unroll
    for (int r = 0; r < 8; r++) {
        int i = i0 + ib + r;
        float2 lo = unpack2(acc2[r][0]);
        float2 hi = unpack2(acc2[r][1]);
        reinterpret_cast<float4*>(&g_pnum[js][i][0])[lane] =
            make_float4(lo.x, lo.y, hi.x, hi.y);
    }
}

// ---------------------------------------------------------------------------
// Kernel C: combine partials, normalize, ELU.
// ---------------------------------------------------------------------------
__global__ __launch_bounds__(256) void combine(float* __restrict__ out) {
    const int idx = blockIdx.x * 256 + threadIdx.x;   // over N*F
    const int i = idx >> 7;
    const int f = idx & (F_OUT - 1);

    float s = 0.0f, d = 0.0f;
    #pragma unroll
    for (int js = 0; js < JSPLIT; js++) {
        s += g_pnum[js][i][f];
        d += g_pden[js][i];
    }
    float v = s / d;
    out[idx] = (v > 0.0f) ? v : expm1f(v);
}

// ---------------------------------------------------------------------------
extern "C" void kernel_launch(void* const* d_in, const int* in_sizes, int n_in,
                              void* d_out, int out_size) {
    const float* h   = (const float*)d_in[0];
    const int*   adj = (const int*)d_in[1];
    const float* W   = (const float*)d_in[2];
    const float* a   = (const float*)d_in[3];
    float* out = (float*)d_out;

    gemm_wh<<<N_NODES / 64, 256>>>(h, W);
    attn_coeffs<<<N_NODES / 8, 256>>>(a);
    aggregate<<<dim3(N_NODES / 64, JSPLIT), 256>>>(adj);
    combine<<<(N_NODES * F_OUT) / 256, 256>>>(out);
}

// round 7
// speedup vs baseline: 2.8825x; 1.8598x over previous
#include <cuda_runtime.h>
#include <cuda_bf16.h>
#include <cstdint>
#include <math.h>

#define N_NODES 8192
#define F_IN    256
#define F_OUT   128
#define NB      136            // GEMM N: 128 feats + den col(128) + 7 zero pad
#define NTILES  (N_NODES / 64) // 128 k-tiles of 64

// ------------------------------ device scratch ------------------------------
__device__ float          g_Wh[N_NODES * F_OUT];        // 4 MB
__device__ float          g_E[N_NODES], g_Ep[N_NODES];  // e^x, e^{0.2x}
__device__ float          g_F[N_NODES], g_Fp[N_NODES];  // e^y, e^{0.2y}
__device__ __nv_bfloat16  g_ybf[N_NODES];               // bf16(y_j)
__device__ uint32_t       g_nx2[N_NODES];               // {bf16(-x_i)} x2
// B planes [mat][NB][8192] bf16; mat: 0=B1hi 1=B1lo 2=B0hi 3=B0lo
__device__ __nv_bfloat16  g_B[4 * NB * N_NODES];        // 8.9 MB

// ------------------------------ asm helpers ---------------------------------
__device__ __forceinline__ uint32_t smem_u32(const void* p) {
    uint32_t a;
    asm("{ .reg .u64 t; cvta.to.shared.u64 t, %1; cvt.u32.u64 %0, t; }"
        : "=r"(a) : "l"(p));
    return a;
}
__device__ __forceinline__ void sts128(uint32_t addr, uint4 v) {
    asm volatile("st.shared.v4.b32 [%0], {%1,%2,%3,%4};"
                 :: "r"(addr), "r"(v.x), "r"(v.y), "r"(v.z), "r"(v.w) : "memory");
}
__device__ __forceinline__ uint32_t set_gt_bf2(uint32_t a, uint32_t b) {
    uint32_t d;
    asm("set.gt.bf16x2.bf16x2 %0, %1, %2;" : "=r"(d) : "r"(a), "r"(b));
    return d;
}
__device__ __forceinline__ uint32_t mul_bf2(uint32_t a, uint32_t b) {
    uint32_t d;
    asm("mul.rn.bf16x2 %0, %1, %2;" : "=r"(d) : "r"(a), "r"(b));
    return d;
}
__device__ __forceinline__ uint32_t sub_bf2(uint32_t a, uint32_t b) {
    uint32_t d;
    asm("sub.rn.bf16x2 %0, %1, %2;" : "=r"(d) : "r"(a), "r"(b));
    return d;
}
__device__ __forceinline__ void ldm4(uint32_t* r, uint32_t addr) {
    asm volatile("ldmatrix.sync.aligned.m8n8.x4.shared.b16 {%0,%1,%2,%3}, [%4];"
                 : "=r"(r[0]), "=r"(r[1]), "=r"(r[2]), "=r"(r[3]) : "r"(addr));
}
__device__ __forceinline__ void ldm2(uint32_t* r, uint32_t addr) {
    asm volatile("ldmatrix.sync.aligned.m8n8.x2.shared.b16 {%0,%1}, [%2];"
                 : "=r"(r[0]), "=r"(r[1]) : "r"(addr));
}
__device__ __forceinline__ void hmma(float* c, const uint32_t* a, const uint32_t* b) {
    asm volatile("mma.sync.aligned.m16n8k16.row.col.f32.bf16.bf16.f32 "
                 "{%0,%1,%2,%3}, {%4,%5,%6,%7}, {%8,%9}, {%0,%1,%2,%3};"
                 : "+f"(c[0]), "+f"(c[1]), "+f"(c[2]), "+f"(c[3])
                 : "r"(a[0]), "r"(a[1]), "r"(a[2]), "r"(a[3]),
                   "r"(b[0]), "r"(b[1]));
}
__device__ __forceinline__ void cpa16(uint32_t dst, const void* src) {
    asm volatile("cp.async.cg.shared.global [%0], [%1], 16;"
                 :: "r"(dst), "l"(src) : "memory");
}
#define CP_COMMIT() asm volatile("cp.async.commit_group;" ::: "memory")
#define CP_WAIT0()  asm volatile("cp.async.wait_group 0;" ::: "memory")

// ---------------------------------------------------------------------------
// Kernel A: Wh = h @ W   (known-good from R2)
// ---------------------------------------------------------------------------
__global__ __launch_bounds__(256) void gemm_wh(const float* __restrict__ h,
                                               const float* __restrict__ W) {
    __shared__ __align__(16) float h_s[64][64];
    __shared__ __align__(16) float W_s[64][F_OUT];

    const int t = threadIdx.x, lane = t & 31, wid = t >> 5;
    const int ib = wid * 8, i0 = blockIdx.x * 64;
    const int tx = t & 63, ty = t >> 6;

    float acc[8][4] = {};
    for (int k0 = 0; k0 < F_IN; k0 += 64) {
        #pragma unroll
        for (int r = 0; r < 16; r++) {
            int i = ty * 16 + r;
            h_s[tx][(i + tx) & 63] = h[(size_t)(i0 + i) * F_IN + k0 + tx];
        }
        {
            const float4* Wg = reinterpret_cast<const float4*>(W + (size_t)k0 * F_OUT);
            float4* Ws4 = reinterpret_cast<float4*>(&W_s[0][0]);
            #pragma unroll
            for (int r = 0; r < 8; r++) Ws4[t + r * 256] = Wg[t + r * 256];
        }
        __syncthreads();
        #pragma unroll 8
        for (int k = 0; k < 64; k++) {
            float4 wv = reinterpret_cast<float4*>(&W_s[k][0])[lane];
            #pragma unroll
            for (int r = 0; r < 8; r++) {
                float hv = h_s[k][(ib + r + k) & 63];
                acc[r][0] += hv * wv.x; acc[r][1] += hv * wv.y;
                acc[r][2] += hv * wv.z; acc[r][3] += hv * wv.w;
            }
        }
        __syncthreads();
    }
    #pragma unroll
    for (int r = 0; r < 8; r++) {
        int i = i0 + ib + r;
        reinterpret_cast<float4*>(&g_Wh[(size_t)i * F_OUT])[lane] =
            make_float4(acc[r][0], acc[r][1], acc[r][2], acc[r][3]);
    }
}

// ---------------------------------------------------------------------------
// Kernel A2: x=Wh.a1, y=Wh.a2 -> E, Ep, F, Fp, bf16 compare keys
// ---------------------------------------------------------------------------
__global__ __launch_bounds__(256) void attn_coeffs(const float* __restrict__ a) {
    const int t = threadIdx.x, lane = t & 31, wid = t >> 5;
    const int i = blockIdx.x * 8 + wid;
    float4 wh = reinterpret_cast<const float4*>(&g_Wh[(size_t)i * F_OUT])[lane];
    float4 a1 = reinterpret_cast<const float4*>(a)[lane];
    float4 a2 = reinterpret_cast<const float4*>(a + F_OUT)[lane];
    float s1 = wh.x * a1.x + wh.y * a1.y + wh.z * a1.z + wh.w * a1.w;
    float s2 = wh.x * a2.x + wh.y * a2.y + wh.z * a2.z + wh.w * a2.w;
    #pragma unroll
    for (int o = 16; o > 0; o >>= 1) {
        s1 += __shfl_xor_sync(0xFFFFFFFFu, s1, o);
        s2 += __shfl_xor_sync(0xFFFFFFFFu, s2, o);
    }
    if (lane == 0) {
        g_E[i]  = expf(s1);
        g_Ep[i] = expf(0.2f * s1);
        g_F[i]  = expf(s2);
        g_Fp[i] = expf(0.2f * s2);
        g_ybf[i] = __float2bfloat16(s2);
        __nv_bfloat16 nb = __float2bfloat16(-s1);
        uint32_t b = (uint32_t)*reinterpret_cast<unsigned short*>(&nb);
        g_nx2[i] = b | (b << 16);
    }
}

// ---------------------------------------------------------------------------
// Kernel A3: build B planes [mat][NB n][8192 j] bf16.
//   n<128:  B1 = F_j*Wh[j][n] (hi/lo), B0 = Fp_j*Wh[j][n] (hi/lo)
//   n=128:  B1 = F_j (hi/lo), B0 = Fp_j (hi/lo)    (denominator column)
//   n=129..135: zero
// ---------------------------------------------------------------------------
__global__ __launch_bounds__(256) void prep_B() {
    __shared__ float s[F_OUT][65];
    __shared__ float sF[64], sFp[64];
    const int t = threadIdx.x;
    const int j0 = blockIdx.x * 64;

    {
        int f4 = (t & 31) * 4;
        int jr = t >> 5;
        #pragma unroll
        for (int p = 0; p < 8; p++) {
            int j = p * 8 + jr;
            float4 v = reinterpret_cast<const float4*>(&g_Wh[(size_t)(j0 + j) * F_OUT])[t & 31];
            s[f4 + 0][j] = v.x; s[f4 + 1][j] = v.y;
            s[f4 + 2][j] = v.z; s[f4 + 3][j] = v.w;
        }
    }
    if (t < 64) { sF[t] = g_F[j0 + t]; sFp[t] = g_Fp[j0 + t]; }
    __syncthreads();

    const int f = t >> 1, half = t & 1;
    #pragma unroll
    for (int q = 0; q < 4; q++) {
        uint32_t b1h[4], b1l[4], b0h[4], b0l[4];
        #pragma unroll
        for (int k = 0; k < 4; k++) {
            int j = half * 32 + q * 8 + k * 2;
            float w0 = s[f][j], w1 = s[f][j + 1];
            float x0 = sF[j] * w0,  x1 = sF[j + 1] * w1;
            float z0 = sFp[j] * w0, z1 = sFp[j + 1] * w1;
            __nv_bfloat162 h1 = __floats2bfloat162_rn(x0, x1);
            __nv_bfloat162 l1 = __floats2bfloat162_rn(x0 - __bfloat162float(h1.x),
                                                      x1 - __bfloat162float(h1.y));
            __nv_bfloat162 h0 = __floats2bfloat162_rn(z0, z1);
            __nv_bfloat162 l0 = __floats2bfloat162_rn(z0 - __bfloat162float(h0.x),
                                                      z1 - __bfloat162float(h0.y));
            b1h[k] = *reinterpret_cast<uint32_t*>(&h1);
            b1l[k] = *reinterpret_cast<uint32_t*>(&l1);
            b0h[k] = *reinterpret_cast<uint32_t*>(&h0);
            b0l[k] = *reinterpret_cast<uint32_t*>(&l0);
        }
        size_t off = (size_t)f * N_NODES + j0 + half * 32 + q * 8;
        *reinterpret_cast<uint4*>(&g_B[((size_t)0 * NB) * N_NODES + off]) = make_uint4(b1h[0], b1h[1], b1h[2], b1h[3]);
        *reinterpret_cast<uint4*>(&g_B[((size_t)1 * NB) * N_NODES + off]) = make_uint4(b1l[0], b1l[1], b1l[2], b1l[3]);
        *reinterpret_cast<uint4*>(&g_B[((size_t)2 * NB) * N_NODES + off]) = make_uint4(b0h[0], b0h[1], b0h[2], b0h[3]);
        *reinterpret_cast<uint4*>(&g_B[((size_t)3 * NB) * N_NODES + off]) = make_uint4(b0l[0], b0l[1], b0l[2], b0l[3]);
    }

    if (t < 64) {
        int j = j0 + t;
        float Fv = sF[t], Fpv = sFp[t];
        __nv_bfloat16 h1 = __float2bfloat16(Fv);
        __nv_bfloat16 l1 = __float2bfloat16(Fv - __bfloat162float(h1));
        __nv_bfloat16 h0 = __float2bfloat16(Fpv);
        __nv_bfloat16 l0 = __float2bfloat16(Fpv - __bfloat162float(h0));
        g_B[((size_t)0 * NB + 128) * N_NODES + j] = h1;
        g_B[((size_t)1 * NB + 128) * N_NODES + j] = l1;
        g_B[((size_t)2 * NB + 128) * N_NODES + j] = h0;
        g_B[((size_t)3 * NB + 128) * N_NODES + j] = l0;
        __nv_bfloat16 z = __float2bfloat16(0.0f);
        #pragma unroll
        for (int r = 129; r < NB; r++)
            #pragma unroll
            for (int m = 0; m < 4; m++)
                g_B[((size_t)m * NB + r) * N_NODES + j] = z;
    }
}

// ---------------------------------------------------------------------------
// Kernel B: tensor-core mask-GEMM aggregation + fused epilogue.
// CTA bx: rows i in [bx*64, +64), all 8192 j, k-tiles of 64.
//   acc1 += M1 @ (B1hi, B1lo);  acc0 += M0 @ (B0hi, B0lo)   (fp32 accum)
//   M1 = adj & (y_j > -x_i)  [bf16 compare],  M0 = adj - M1   (exact 0/1)
// out[i][f] = elu( (E_i*acc1 + Ep_i*acc0)[f] / (E_i*acc1 + Ep_i*acc0)[128] )
// ---------------------------------------------------------------------------
__global__ __launch_bounds__(256, 1) void aggregate(const int* __restrict__ adj,
                                                    float* __restrict__ out) {
    extern __shared__ __align__(1024) char smem[];
    const uint32_t sb = smem_u32(smem);
    // [0, 32768):       A buffers (2 x {M1 8KB, M0 8KB})
    // [32768, 172032):  B buffers (2 x 4 planes x 17408 B)
    // [172032, 172288): den_sm (64 floats)
    float* den_sm = reinterpret_cast<float*>(smem + 172032);

    const int t = threadIdx.x, lane = t & 31, wid = t >> 5;
    const int wm = wid & 3, wn = wid >> 2;
    const int i0 = blockIdx.x * 64;

    const int i_my = t >> 2;   // 0..63
    const int jq   = t & 3;    // 16-j quarter

    const uint32_t nx2 = g_nx2[i0 + i_my];

    float acc1[9][4], acc0[9][4];
    #pragma unroll
    for (int n = 0; n < 9; n++)
        #pragma unroll
        for (int c = 0; c < 4; c++) { acc1[n][c] = 0.0f; acc0[n][c] = 0.0f; }

    // B cp.async issue for one tile into buffer p
    auto issue_b = [&](int j0t, int p) {
        const uint32_t BB = sb + 32768 + p * 69632;
        #pragma unroll
        for (int k = 0; k < 16; k++) {
            int plane = k >> 2;
            int rem = (k & 3) * 256 + t;
            int n = rem >> 3, ch = rem & 7;
            const void* src = &g_B[((size_t)plane * NB + n) * N_NODES + j0t + ch * 8];
            uint32_t dst = BB + plane * 17408 + n * 128 + ((ch ^ (n & 7)) << 4);
            cpa16(dst, src);
        }
        {   // leftover: n = 128..135
            int plane = t >> 6;
            int n = 128 + ((t & 63) >> 3), ch = t & 7;
            const void* src = &g_B[((size_t)plane * NB + n) * N_NODES + j0t + ch * 8];
            uint32_t dst = BB + plane * 17408 + n * 128 + ((ch ^ (n & 7)) << 4);
            cpa16(dst, src);
        }
    };

    // prologue: adj tile 0 prefetch + B tile 0 cp.async
    int4 adjv[4];
    {
        const int4* ap = reinterpret_cast<const int4*>(
            adj + (size_t)(i0 + i_my) * N_NODES + jq * 16);
        #pragma unroll
        for (int q = 0; q < 4; q++) adjv[q] = ap[q];
    }
    issue_b(0, 0);
    CP_COMMIT();

    for (int tl = 0; tl < NTILES; tl++) {
        const int p = tl & 1;
        const int j0 = tl * 64;
        const uint32_t A1 = sb + p * 16384;
        const uint32_t A0 = A1 + 8192;
        const uint32_t BB = sb + 32768 + p * 69632;

        CP_WAIT0();   // this tile's B planes have landed

        // ---- build masks for this tile ----
        {
            const uint32_t* yb = reinterpret_cast<const uint32_t*>(g_ybf + j0 + jq * 16);
            uint32_t m1r[8], m0r[8];
            #pragma unroll
            for (int q = 0; q < 4; q++) {
                int4 av = adjv[q];
                uint32_t y01 = yb[2 * q], y23 = yb[2 * q + 1];
                uint32_t u01 = (uint32_t)av.x | ((uint32_t)av.y << 16);
                uint32_t u23 = (uint32_t)av.z | ((uint32_t)av.w << 16);
                uint32_t a01 = u01 * 0x3F80u, a23 = u23 * 0x3F80u;  // bf16 1.0 per set half
                uint32_t p01 = set_gt_bf2(y01, nx2), p23 = set_gt_bf2(y23, nx2);
                uint32_t q01 = mul_bf2(a01, p01), q23 = mul_bf2(a23, p23);
                m1r[2 * q] = q01;            m1r[2 * q + 1] = q23;
                m0r[2 * q] = sub_bf2(a01, q01); m0r[2 * q + 1] = sub_bf2(a23, q23);
            }
            uint32_t rowb = (uint32_t)i_my * 128;
            uint32_t so0 = (uint32_t)(((2 * jq)     ^ (i_my & 7)) << 4);
            uint32_t so1 = (uint32_t)(((2 * jq + 1) ^ (i_my & 7)) << 4);
            sts128(A1 + rowb + so0, make_uint4(m1r[0], m1r[1], m1r[2], m1r[3]));
            sts128(A1 + rowb + so1, make_uint4(m1r[4], m1r[5], m1r[6], m1r[7]));
            sts128(A0 + rowb + so0, make_uint4(m0r[0], m0r[1], m0r[2], m0r[3]));
            sts128(A0 + rowb + so1, make_uint4(m0r[4], m0r[5], m0r[6], m0r[7]));
        }
        __syncthreads();

        // ---- prefetch next tile (overlaps compute below) ----
        if (tl + 1 < NTILES) {
            const int jn = j0 + 64;
            const int4* ap = reinterpret_cast<const int4*>(
                adj + (size_t)(i0 + i_my) * N_NODES + jn + jq * 16);
            #pragma unroll
            for (int q = 0; q < 4; q++) adjv[q] = ap[q];
            issue_b(jn, (tl + 1) & 1);
        }
        CP_COMMIT();

        // ---- compute: 4 k-steps x 4 planes x n-tiles ----
        #define PLANE_MMAS(PL, AF, AC) do {                                              \
            const uint32_t Bp = BB + (PL) * 17408;                                       \
            _Pragma("unroll")                                                            \
            for (int np = 0; np < 4; np++) {                                             \
                int gt = wn ? (8 + 2 * np) : (2 * np);                                   \
                uint32_t nrow = (uint32_t)(gt + (lane >> 4)) * 8 + (lane & 7);           \
                uint32_t bch = (uint32_t)(ks * 2 + ((lane >> 3) & 1));                   \
                uint32_t baddr = Bp + nrow * 128 + ((bch ^ (nrow & 7)) << 4);            \
                uint32_t bf[4]; ldm4(bf, baddr);                                         \
                hmma(AC[2 * np], AF, bf);                                                \
                hmma(AC[2 * np + 1], AF, bf + 2);                                        \
            }                                                                            \
            if (wn == 0) {                                                               \
                uint32_t nrow = 128 + (lane & 7);                                        \
                uint32_t bch = (uint32_t)(ks * 2 + ((lane >> 3) & 1));                   \
                uint32_t baddr = Bp + nrow * 128 + ((bch ^ (nrow & 7)) << 4);            \
                uint32_t bf[2]; ldm2(bf, baddr);                                         \
                hmma(AC[8], AF, bf);                                                     \
            }                                                                            \
        } while (0)

        #pragma unroll
        for (int ks = 0; ks < 4; ks++) {
            uint32_t am1[4], am0[4];
            uint32_t arow = (uint32_t)(wm * 16 + (lane & 7) + ((lane >> 3) & 1) * 8);
            uint32_t ach = (uint32_t)(ks * 2 + (lane >> 4));
            uint32_t aoff = arow * 128 + ((ach ^ (arow & 7)) << 4);
            ldm4(am1, A1 + aoff);
            ldm4(am0, A0 + aoff);
            PLANE_MMAS(0, am1, acc1);
            PLANE_MMAS(1, am1, acc1);
            PLANE_MMAS(2, am0, acc0);
            PLANE_MMAS(3, am0, acc0);
        }
        #undef PLANE_MMAS
    }

    // ---- epilogue: den broadcast, scale, normalize, ELU, store ----
    const int r0 = wm * 16 + (lane >> 2);
    const int r1 = r0 + 8;
    const float E0 = g_E[i0 + r0], Ep0 = g_Ep[i0 + r0];
    const float E1 = g_E[i0 + r1], Ep1 = g_Ep[i0 + r1];

    if (wn == 0 && (lane & 3) == 0) {
        den_sm[r0] = E0 * acc1[8][0] + Ep0 * acc0[8][0];
        den_sm[r1] = E1 * acc1[8][2] + Ep1 * acc0[8][2];
    }
    __syncthreads();
    const float id0 = 1.0f / den_sm[r0];
    const float id1 = 1.0f / den_sm[r1];

    #pragma unroll
    for (int ntl = 0; ntl < 8; ntl++) {
        int n = (wn ? 64 + ntl * 8 : ntl * 8) + (lane & 3) * 2;
        float v00 = (E0 * acc1[ntl][0] + Ep0 * acc0[ntl][0]) * id0;
        float v01 = (E0 * acc1[ntl][1] + Ep0 * acc0[ntl][1]) * id0;
        float v10 = (E1 * acc1[ntl][2] + Ep1 * acc0[ntl][2]) * id1;
        float v11 = (E1 * acc1[ntl][3] + Ep1 * acc0[ntl][3]) * id1;
        v00 = (v00 > 0.0f) ? v00 : expm1f(v00);
        v01 = (v01 > 0.0f) ? v01 : expm1f(v01);
        v10 = (v10 > 0.0f) ? v10 : expm1f(v10);
        v11 = (v11 > 0.0f) ? v11 : expm1f(v11);
        *reinterpret_cast<float2*>(&out[(size_t)(i0 + r0) * F_OUT + n]) = make_float2(v00, v01);
        *reinterpret_cast<float2*>(&out[(size_t)(i0 + r1) * F_OUT + n]) = make_float2(v10, v11);
    }
}

// ---------------------------------------------------------------------------
extern "C" void kernel_launch(void* const* d_in, const int* in_sizes, int n_in,
                              void* d_out, int out_size) {
    const float* h   = (const float*)d_in[0];
    const int*   adj = (const int*)d_in[1];
    const float* W   = (const float*)d_in[2];
    const float* a   = (const float*)d_in[3];
    float* out = (float*)d_out;

    const int AGG_SMEM = 172288;
    static int configured = 0;
    cudaFuncSetAttribute(aggregate, cudaFuncAttributeMaxDynamicSharedMemorySize, AGG_SMEM);
    (void)configured;

    gemm_wh<<<N_NODES / 64, 256>>>(h, W);
    attn_coeffs<<<N_NODES / 8, 256>>>(a);
    prep_B<<<N_NODES / 64, 256>>>();
    aggregate<<<N_NODES / 64, 256, AGG_SMEM>>>(adj, out);
}

// round 12
// speedup vs baseline: 3.0682x; 1.0644x over previous
#include <cuda_runtime.h>
#include <cuda_bf16.h>
#include <cstdint>
#include <math.h>

#define N_NODES 8192
#define F_IN    256
#define F_OUT   128
#define NB      136            // GEMM N: 128 feats + den col(128) + 7 zero pad
#define NTILES  (N_NODES / 64) // 128 k-tiles of 64

// ------------------------------ device scratch ------------------------------
__device__ float          g_Wh[N_NODES * F_OUT];        // 4 MB
__device__ float          g_E[N_NODES], g_Ep[N_NODES];  // e^x, e^{0.2x}
__device__ float          g_F[N_NODES], g_Fp[N_NODES];  // e^y, e^{0.2y}
__device__ __nv_bfloat16  g_ybf[N_NODES];               // bf16(y_j)
__device__ uint32_t       g_nx2[N_NODES];               // {bf16(-x_i)} x2
// B planes [mat][NB][8192] bf16; mat: 0=B1hi 1=B1lo 2=B0hi 3=B0lo
__device__ __nv_bfloat16  g_B[4 * NB * N_NODES];        // 8.9 MB

// ------------------------------ asm helpers ---------------------------------
__device__ __forceinline__ uint32_t smem_u32(const void* p) {
    uint32_t a;
    asm("{ .reg .u64 t; cvta.to.shared.u64 t, %1; cvt.u32.u64 %0, t; }"
        : "=r"(a) : "l"(p));
    return a;
}
__device__ __forceinline__ void sts128(uint32_t addr, uint4 v) {
    asm volatile("st.shared.v4.b32 [%0], {%1,%2,%3,%4};"
                 :: "r"(addr), "r"(v.x), "r"(v.y), "r"(v.z), "r"(v.w) : "memory");
}
__device__ __forceinline__ uint32_t set_gt_bf2(uint32_t a, uint32_t b) {
    uint32_t d;
    asm("set.gt.bf16x2.bf16x2 %0, %1, %2;" : "=r"(d) : "r"(a), "r"(b));
    return d;
}
__device__ __forceinline__ uint32_t mul_bf2(uint32_t a, uint32_t b) {
    uint32_t d;
    asm("mul.rn.bf16x2 %0, %1, %2;" : "=r"(d) : "r"(a), "r"(b));
    return d;
}
__device__ __forceinline__ uint32_t sub_bf2(uint32_t a, uint32_t b) {
    uint32_t d;
    asm("sub.rn.bf16x2 %0, %1, %2;" : "=r"(d) : "r"(a), "r"(b));
    return d;
}
__device__ __forceinline__ void ldm4(uint32_t* r, uint32_t addr) {
    asm volatile("ldmatrix.sync.aligned.m8n8.x4.shared.b16 {%0,%1,%2,%3}, [%4];"
                 : "=r"(r[0]), "=r"(r[1]), "=r"(r[2]), "=r"(r[3]) : "r"(addr));
}
__device__ __forceinline__ void ldm2(uint32_t* r, uint32_t addr) {
    asm volatile("ldmatrix.sync.aligned.m8n8.x2.shared.b16 {%0,%1}, [%2];"
                 : "=r"(r[0]), "=r"(r[1]) : "r"(addr));
}
__device__ __forceinline__ void hmma(float* c, const uint32_t* a, const uint32_t* b) {
    asm volatile("mma.sync.aligned.m16n8k16.row.col.f32.bf16.bf16.f32 "
                 "{%0,%1,%2,%3}, {%4,%5,%6,%7}, {%8,%9}, {%0,%1,%2,%3};"
                 : "+f"(c[0]), "+f"(c[1]), "+f"(c[2]), "+f"(c[3])
                 : "r"(a[0]), "r"(a[1]), "r"(a[2]), "r"(a[3]),
                   "r"(b[0]), "r"(b[1]));
}
__device__ __forceinline__ void cpa16(uint32_t dst, const void* src) {
    asm volatile("cp.async.cg.shared.global [%0], [%1], 16;"
                 :: "r"(dst), "l"(src) : "memory");
}
#define CP_COMMIT() asm volatile("cp.async.commit_group;" ::: "memory")
#define CP_WAIT0()  asm volatile("cp.async.wait_group 0;" ::: "memory")

// ---------------------------------------------------------------------------
// Kernel A: Wh = h @ W   (known-good from R2)
// ---------------------------------------------------------------------------
__global__ __launch_bounds__(256) void gemm_wh(const float* __restrict__ h,
                                               const float* __restrict__ W) {
    __shared__ __align__(16) float h_s[64][64];
    __shared__ __align__(16) float W_s[64][F_OUT];

    const int t = threadIdx.x, lane = t & 31, wid = t >> 5;
    const int ib = wid * 8, i0 = blockIdx.x * 64;
    const int tx = t & 63, ty = t >> 6;

    float acc[8][4] = {};
    for (int k0 = 0; k0 < F_IN; k0 += 64) {
        #pragma unroll
        for (int r = 0; r < 16; r++) {
            int i = ty * 16 + r;
            h_s[tx][(i + tx) & 63] = h[(size_t)(i0 + i) * F_IN + k0 + tx];
        }
        {
            const float4* Wg = reinterpret_cast<const float4*>(W + (size_t)k0 * F_OUT);
            float4* Ws4 = reinterpret_cast<float4*>(&W_s[0][0]);
            #pragma unroll
            for (int r = 0; r < 8; r++) Ws4[t + r * 256] = Wg[t + r * 256];
        }
        __syncthreads();
        #pragma unroll 8
        for (int k = 0; k < 64; k++) {
            float4 wv = reinterpret_cast<float4*>(&W_s[k][0])[lane];
            #pragma unroll
            for (int r = 0; r < 8; r++) {
                float hv = h_s[k][(ib + r + k) & 63];
                acc[r][0] += hv * wv.x; acc[r][1] += hv * wv.y;
                acc[r][2] += hv * wv.z; acc[r][3] += hv * wv.w;
            }
        }
        __syncthreads();
    }
    #pragma unroll
    for (int r = 0; r < 8; r++) {
        int i = i0 + ib + r;
        reinterpret_cast<float4*>(&g_Wh[(size_t)i * F_OUT])[lane] =
            make_float4(acc[r][0], acc[r][1], acc[r][2], acc[r][3]);
    }
}

// ---------------------------------------------------------------------------
// Kernel A2: x=Wh.a1, y=Wh.a2 -> E, Ep, F, Fp, bf16 compare keys
// ---------------------------------------------------------------------------
__global__ __launch_bounds__(256) void attn_coeffs(const float* __restrict__ a) {
    const int t = threadIdx.x, lane = t & 31, wid = t >> 5;
    const int i = blockIdx.x * 8 + wid;
    float4 wh = reinterpret_cast<const float4*>(&g_Wh[(size_t)i * F_OUT])[lane];
    float4 a1 = reinterpret_cast<const float4*>(a)[lane];
    float4 a2 = reinterpret_cast<const float4*>(a + F_OUT)[lane];
    float s1 = wh.x * a1.x + wh.y * a1.y + wh.z * a1.z + wh.w * a1.w;
    float s2 = wh.x * a2.x + wh.y * a2.y + wh.z * a2.z + wh.w * a2.w;
    #pragma unroll
    for (int o = 16; o > 0; o >>= 1) {
        s1 += __shfl_xor_sync(0xFFFFFFFFu, s1, o);
        s2 += __shfl_xor_sync(0xFFFFFFFFu, s2, o);
    }
    if (lane == 0) {
        g_E[i]  = expf(s1);
        g_Ep[i] = expf(0.2f * s1);
        g_F[i]  = expf(s2);
        g_Fp[i] = expf(0.2f * s2);
        g_ybf[i] = __float2bfloat16(s2);
        __nv_bfloat16 nb = __float2bfloat16(-s1);
        uint32_t b = (uint32_t)*reinterpret_cast<unsigned short*>(&nb);
        g_nx2[i] = b | (b << 16);
    }
}

// ---------------------------------------------------------------------------
// Kernel A3: build B planes [mat][NB n][8192 j] bf16.
// ---------------------------------------------------------------------------
__global__ __launch_bounds__(256) void prep_B() {
    __shared__ float s[F_OUT][65];
    __shared__ float sF[64], sFp[64];
    const int t = threadIdx.x;
    const int j0 = blockIdx.x * 64;

    {
        int f4 = (t & 31) * 4;
        int jr = t >> 5;
        #pragma unroll
        for (int p = 0; p < 8; p++) {
            int j = p * 8 + jr;
            float4 v = reinterpret_cast<const float4*>(&g_Wh[(size_t)(j0 + j) * F_OUT])[t & 31];
            s[f4 + 0][j] = v.x; s[f4 + 1][j] = v.y;
            s[f4 + 2][j] = v.z; s[f4 + 3][j] = v.w;
        }
    }
    if (t < 64) { sF[t] = g_F[j0 + t]; sFp[t] = g_Fp[j0 + t]; }
    __syncthreads();

    const int f = t >> 1, half = t & 1;
    #pragma unroll
    for (int q = 0; q < 4; q++) {
        uint32_t b1h[4], b1l[4], b0h[4], b0l[4];
        #pragma unroll
        for (int k = 0; k < 4; k++) {
            int j = half * 32 + q * 8 + k * 2;
            float w0 = s[f][j], w1 = s[f][j + 1];
            float x0 = sF[j] * w0,  x1 = sF[j + 1] * w1;
            float z0 = sFp[j] * w0, z1 = sFp[j + 1] * w1;
            __nv_bfloat162 h1 = __floats2bfloat162_rn(x0, x1);
            __nv_bfloat162 l1 = __floats2bfloat162_rn(x0 - __bfloat162float(h1.x),
                                                      x1 - __bfloat162float(h1.y));
            __nv_bfloat162 h0 = __floats2bfloat162_rn(z0, z1);
            __nv_bfloat162 l0 = __floats2bfloat162_rn(z0 - __bfloat162float(h0.x),
                                                      z1 - __bfloat162float(h0.y));
            b1h[k] = *reinterpret_cast<uint32_t*>(&h1);
            b1l[k] = *reinterpret_cast<uint32_t*>(&l1);
            b0h[k] = *reinterpret_cast<uint32_t*>(&h0);
            b0l[k] = *reinterpret_cast<uint32_t*>(&l0);
        }
        size_t off = (size_t)f * N_NODES + j0 + half * 32 + q * 8;
        *reinterpret_cast<uint4*>(&g_B[((size_t)0 * NB) * N_NODES + off]) = make_uint4(b1h[0], b1h[1], b1h[2], b1h[3]);
        *reinterpret_cast<uint4*>(&g_B[((size_t)1 * NB) * N_NODES + off]) = make_uint4(b1l[0], b1l[1], b1l[2], b1l[3]);
        *reinterpret_cast<uint4*>(&g_B[((size_t)2 * NB) * N_NODES + off]) = make_uint4(b0h[0], b0h[1], b0h[2], b0h[3]);
        *reinterpret_cast<uint4*>(&g_B[((size_t)3 * NB) * N_NODES + off]) = make_uint4(b0l[0], b0l[1], b0l[2], b0l[3]);
    }

    if (t < 64) {
        int j = j0 + t;
        float Fv = sF[t], Fpv = sFp[t];
        __nv_bfloat16 h1 = __float2bfloat16(Fv);
        __nv_bfloat16 l1 = __float2bfloat16(Fv - __bfloat162float(h1));
        __nv_bfloat16 h0 = __float2bfloat16(Fpv);
        __nv_bfloat16 l0 = __float2bfloat16(Fpv - __bfloat162float(h0));
        g_B[((size_t)0 * NB + 128) * N_NODES + j] = h1;
        g_B[((size_t)1 * NB + 128) * N_NODES + j] = l1;
        g_B[((size_t)2 * NB + 128) * N_NODES + j] = h0;
        g_B[((size_t)3 * NB + 128) * N_NODES + j] = l0;
        __nv_bfloat16 z = __float2bfloat16(0.0f);
        #pragma unroll
        for (int r = 129; r < NB; r++)
            #pragma unroll
            for (int m = 0; m < 4; m++)
                g_B[((size_t)m * NB + r) * N_NODES + j] = z;
    }
}

// ---------------------------------------------------------------------------
// Kernel B: tensor-core mask-GEMM aggregation + fused epilogue.
// 512 threads = 16 warps: wm = wid&3 (m 16-row tiles), wn = wid>>2 (n 32-col
// quarters).  4 warps/SMSP for latency hiding (R7 ran 2/SMSP, tensor=38%).
// ---------------------------------------------------------------------------
__global__ __launch_bounds__(512, 1) void aggregate(const int* __restrict__ adj,
                                                    float* __restrict__ out) {
    extern __shared__ __align__(1024) char smem[];
    const uint32_t sb = smem_u32(smem);
    // [0, 32768):       A buffers (2 x {M1 8KB, M0 8KB})
    // [32768, 172032):  B buffers (2 x 4 planes x 17408 B)
    // [172032, 172288): den_sm (64 floats)
    float* den_sm = reinterpret_cast<float*>(smem + 172032);

    const int t = threadIdx.x, lane = t & 31, wid = t >> 5;
    const int wm = wid & 3, wn = wid >> 2;       // 4 x 4 warp grid
    const int i0 = blockIdx.x * 64;

    const int i_my = t >> 3;   // 0..63
    const int jq   = t & 7;    // 8-j chunk

    const uint32_t nx2 = g_nx2[i0 + i_my];

    float acc1[5][4], acc0[5][4];
    #pragma unroll
    for (int n = 0; n < 5; n++)
        #pragma unroll
        for (int c = 0; c < 4; c++) { acc1[n][c] = 0.0f; acc0[n][c] = 0.0f; }

    // B cp.async issue for one tile into buffer p (4352 16B-chunks, 512 thr)
    auto issue_b = [&](int j0t, int p) {
        const uint32_t BB = sb + 32768 + p * 69632;
        #pragma unroll
        for (int k = 0; k < 8; k++) {
            int c = k * 512 + t;
            int plane = c / 1088;
            int rem = c - plane * 1088;
            int n = rem >> 3, ch = rem & 7;
            const void* src = &g_B[((size_t)plane * NB + n) * N_NODES + j0t + ch * 8];
            uint32_t dst = BB + plane * 17408 + n * 128 + ((ch ^ (n & 7)) << 4);
            cpa16(dst, src);
        }
        if (t < 256) {   // leftover: plane 3 tail
            int rem = 832 + t;
            int n = rem >> 3, ch = rem & 7;
            const void* src = &g_B[((size_t)3 * NB + n) * N_NODES + j0t + ch * 8];
            uint32_t dst = BB + 3 * 17408 + n * 128 + ((ch ^ (n & 7)) << 4);
            cpa16(dst, src);
        }
    };

    // prologue: adj tile 0 prefetch + B tile 0 cp.async
    int4 adjv[2];
    {
        const int4* ap = reinterpret_cast<const int4*>(
            adj + (size_t)(i0 + i_my) * N_NODES + jq * 8);
        adjv[0] = ap[0]; adjv[1] = ap[1];
    }
    issue_b(0, 0);
    CP_COMMIT();

    for (int tl = 0; tl < NTILES; tl++) {
        const int p = tl & 1;
        const int j0 = tl * 64;
        const uint32_t A1 = sb + p * 16384;
        const uint32_t A0 = A1 + 8192;
        const uint32_t BB = sb + 32768 + p * 69632;

        CP_WAIT0();   // this tile's B planes have landed

        // ---- build masks (each thread: 8 j's for one i-row) ----
        {
            const uint32_t* yb = reinterpret_cast<const uint32_t*>(g_ybf + j0 + jq * 8);
            uint32_t m1r[4], m0r[4];
            #pragma unroll
            for (int q = 0; q < 2; q++) {
                int4 av = adjv[q];
                uint32_t y01 = yb[2 * q], y23 = yb[2 * q + 1];
                uint32_t u01 = (uint32_t)av.x | ((uint32_t)av.y << 16);
                uint32_t u23 = (uint32_t)av.z | ((uint32_t)av.w << 16);
                uint32_t a01 = u01 * 0x3F80u, a23 = u23 * 0x3F80u;  // bf16 1.0 per set half
                uint32_t p01 = set_gt_bf2(y01, nx2), p23 = set_gt_bf2(y23, nx2);
                uint32_t q01 = mul_bf2(a01, p01), q23 = mul_bf2(a23, p23);
                m1r[2 * q] = q01;               m1r[2 * q + 1] = q23;
                m0r[2 * q] = sub_bf2(a01, q01); m0r[2 * q + 1] = sub_bf2(a23, q23);
            }
            uint32_t rowb = (uint32_t)i_my * 128;
            uint32_t so = (uint32_t)((jq ^ (i_my & 7)) << 4);
            sts128(A1 + rowb + so, make_uint4(m1r[0], m1r[1], m1r[2], m1r[3]));
            sts128(A0 + rowb + so, make_uint4(m0r[0], m0r[1], m0r[2], m0r[3]));
        }
        __syncthreads();

        // ---- prefetch next tile (overlaps compute below) ----
        if (tl + 1 < NTILES) {
            const int jn = j0 + 64;
            const int4* ap = reinterpret_cast<const int4*>(
                adj + (size_t)(i0 + i_my) * N_NODES + jn + jq * 8);
            adjv[0] = ap[0]; adjv[1] = ap[1];
            issue_b(jn, (tl + 1) & 1);
        }
        CP_COMMIT();

        // ---- compute: 4 k-steps x 4 planes x 2 n-subtiles (+den for wn==0) --
        #define PLANE_MMAS(PL, AF, AC) do {                                              \
            const uint32_t Bp = BB + (PL) * 17408;                                       \
            _Pragma("unroll")                                                            \
            for (int np = 0; np < 2; np++) {                                             \
                uint32_t nrow = (uint32_t)(wn * 4 + np * 2 + (lane >> 4)) * 8 + (lane & 7); \
                uint32_t bch = (uint32_t)(ks * 2 + ((lane >> 3) & 1));                   \
                uint32_t baddr = Bp + nrow * 128 + ((bch ^ (nrow & 7)) << 4);            \
                uint32_t bf[4]; ldm4(bf, baddr);                                         \
                hmma(AC[2 * np], AF, bf);                                                \
                hmma(AC[2 * np + 1], AF, bf + 2);                                        \
            }                                                                            \
            if (wn == 0) {                                                               \
                uint32_t nrow = 128 + (lane & 7);                                        \
                uint32_t bch = (uint32_t)(ks * 2 + ((lane >> 3) & 1));                   \
                uint32_t baddr = Bp + nrow * 128 + ((bch ^ (nrow & 7)) << 4);            \
                uint32_t bf[2]; ldm2(bf, baddr);                                         \
                hmma(AC[4], AF, bf);                                                     \
            }                                                                            \
        } while (0)

        #pragma unroll
        for (int ks = 0; ks < 4; ks++) {
            uint32_t am1[4], am0[4];
            uint32_t arow = (uint32_t)(wm * 16 + (lane & 7) + ((lane >> 3) & 1) * 8);
            uint32_t ach = (uint32_t)(ks * 2 + (lane >> 4));
            uint32_t aoff = arow * 128 + ((ach ^ (arow & 7)) << 4);
            ldm4(am1, A1 + aoff);
            ldm4(am0, A0 + aoff);
            PLANE_MMAS(0, am1, acc1);
            PLANE_MMAS(1, am1, acc1);
            PLANE_MMAS(2, am0, acc0);
            PLANE_MMAS(3, am0, acc0);
        }
        #undef PLANE_MMAS
    }

    // ---- epilogue: den broadcast, scale, normalize, ELU, store ----
    const int r0 = wm * 16 + (lane >> 2);
    const int r1 = r0 + 8;
    const float E0 = g_E[i0 + r0], Ep0 = g_Ep[i0 + r0];
    const float E1 = g_E[i0 + r1], Ep1 = g_Ep[i0 + r1];

    if (wn == 0 && (lane & 3) == 0) {
        den_sm[r0] = E0 * acc1[4][0] + Ep0 * acc0[4][0];
        den_sm[r1] = E1 * acc1[4][2] + Ep1 * acc0[4][2];
    }
    __syncthreads();
    const float id0 = 1.0f / den_sm[r0];
    const float id1 = 1.0f / den_sm[r1];

    #pragma unroll
    for (int ntl = 0; ntl < 4; ntl++) {
        int n = wn * 32 + ntl * 8 + (lane & 3) * 2;
        float v00 = (E0 * acc1[ntl][0] + Ep0 * acc0[ntl][0]) * id0;
        float v01 = (E0 * acc1[ntl][1] + Ep0 * acc0[ntl][1]) * id0;
        float v10 = (E1 * acc1[ntl][2] + Ep1 * acc0[ntl][2]) * id1;
        float v11 = (E1 * acc1[ntl][3] + Ep1 * acc0[ntl][3]) * id1;
        v00 = (v00 > 0.0f) ? v00 : expm1f(v00);
        v01 = (v01 > 0.0f) ? v01 : expm1f(v01);
        v10 = (v10 > 0.0f) ? v10 : expm1f(v10);
        v11 = (v11 > 0.0f) ? v11 : expm1f(v11);
        *reinterpret_cast<float2*>(&out[(size_t)(i0 + r0) * F_OUT + n]) = make_float2(v00, v01);
        *reinterpret_cast<float2*>(&out[(size_t)(i0 + r1) * F_OUT + n]) = make_float2(v10, v11);
    }
}

// ---------------------------------------------------------------------------
extern "C" void kernel_launch(void* const* d_in, const int* in_sizes, int n_in,
                              void* d_out, int out_size) {
    const float* h   = (const float*)d_in[0];
    const int*   adj = (const int*)d_in[1];
    const float* W   = (const float*)d_in[2];
    const float* a   = (const float*)d_in[3];
    float* out = (float*)d_out;

    const int AGG_SMEM = 172288;
    cudaFuncSetAttribute(aggregate, cudaFuncAttributeMaxDynamicSharedMemorySize, AGG_SMEM);

    gemm_wh<<<N_NODES / 64, 256>>>(h, W);
    attn_coeffs<<<N_NODES / 8, 256>>>(a);
    prep_B<<<N_NODES / 64, 256>>>();
    aggregate<<<N_NODES / 64, 512, AGG_SMEM>>>(adj, out);
}

// round 13
// speedup vs baseline: 3.5745x; 1.1650x over previous
#include <cuda_runtime.h>
#include <cuda_bf16.h>
#include <cstdint>
#include <math.h>

#define N_NODES 8192
#define F_IN    256
#define F_OUT   128
#define NB      136            // GEMM N: 128 feats + den col(128) + 7 zero pad
#define NTILES  (N_NODES / 64) // 128 k-tiles of 64

// ------------------------------ device scratch ------------------------------
__device__ float          g_Wh[N_NODES * F_OUT];        // 4 MB
__device__ float          g_E[N_NODES], g_Ep[N_NODES];  // e^x, e^{0.2x}
__device__ float          g_F[N_NODES], g_Fp[N_NODES];  // e^y, e^{0.2y}
__device__ __nv_bfloat16  g_ybf[N_NODES];               // bf16(y_j)
__device__ uint32_t       g_nx2[N_NODES];               // {bf16(-x_i)} x2
// B planes [mat][NB][8192] bf16; mat: 0=B1hi 1=B1lo 2=B0hi 3=B0lo
__device__ __nv_bfloat16  g_B[4 * NB * N_NODES];        // 8.9 MB

// ------------------------------ asm helpers ---------------------------------
__device__ __forceinline__ uint32_t smem_u32(const void* p) {
    uint32_t a;
    asm("{ .reg .u64 t; cvta.to.shared.u64 t, %1; cvt.u32.u64 %0, t; }"
        : "=r"(a) : "l"(p));
    return a;
}
__device__ __forceinline__ void sts128(uint32_t addr, uint4 v) {
    asm volatile("st.shared.v4.b32 [%0], {%1,%2,%3,%4};"
                 :: "r"(addr), "r"(v.x), "r"(v.y), "r"(v.z), "r"(v.w) : "memory");
}
__device__ __forceinline__ uint32_t set_gt_bf2(uint32_t a, uint32_t b) {
    uint32_t d;
    asm("set.gt.bf16x2.bf16x2 %0, %1, %2;" : "=r"(d) : "r"(a), "r"(b));
    return d;
}
__device__ __forceinline__ uint32_t mul_bf2(uint32_t a, uint32_t b) {
    uint32_t d;
    asm("mul.rn.bf16x2 %0, %1, %2;" : "=r"(d) : "r"(a), "r"(b));
    return d;
}
__device__ __forceinline__ uint32_t sub_bf2(uint32_t a, uint32_t b) {
    uint32_t d;
    asm("sub.rn.bf16x2 %0, %1, %2;" : "=r"(d) : "r"(a), "r"(b));
    return d;
}
__device__ __forceinline__ void ldm4(uint32_t* r, uint32_t addr) {
    asm volatile("ldmatrix.sync.aligned.m8n8.x4.shared.b16 {%0,%1,%2,%3}, [%4];"
                 : "=r"(r[0]), "=r"(r[1]), "=r"(r[2]), "=r"(r[3]) : "r"(addr));
}
__device__ __forceinline__ void ldm2(uint32_t* r, uint32_t addr) {
    asm volatile("ldmatrix.sync.aligned.m8n8.x2.shared.b16 {%0,%1}, [%2];"
                 : "=r"(r[0]), "=r"(r[1]) : "r"(addr));
}
__device__ __forceinline__ void hmma(float* c, const uint32_t* a, const uint32_t* b) {
    asm volatile("mma.sync.aligned.m16n8k16.row.col.f32.bf16.bf16.f32 "
                 "{%0,%1,%2,%3}, {%4,%5,%6,%7}, {%8,%9}, {%0,%1,%2,%3};"
                 : "+f"(c[0]), "+f"(c[1]), "+f"(c[2]), "+f"(c[3])
                 : "r"(a[0]), "r"(a[1]), "r"(a[2]), "r"(a[3]),
                   "r"(b[0]), "r"(b[1]));
}
__device__ __forceinline__ void cpa16(uint32_t dst, const void* src) {
    asm volatile("cp.async.cg.shared.global [%0], [%1], 16;"
                 :: "r"(dst), "l"(src) : "memory");
}
#define CP_COMMIT() asm volatile("cp.async.commit_group;" ::: "memory")
#define CP_WAIT0()  asm volatile("cp.async.wait_group 0;" ::: "memory")

// ---------------------------------------------------------------------------
// Kernel A: Wh = h @ W   (known-good)
// ---------------------------------------------------------------------------
__global__ __launch_bounds__(256) void gemm_wh(const float* __restrict__ h,
                                               const float* __restrict__ W) {
    __shared__ __align__(16) float h_s[64][64];
    __shared__ __align__(16) float W_s[64][F_OUT];

    const int t = threadIdx.x, lane = t & 31, wid = t >> 5;
    const int ib = wid * 8, i0 = blockIdx.x * 64;
    const int tx = t & 63, ty = t >> 6;

    float acc[8][4] = {};
    for (int k0 = 0; k0 < F_IN; k0 += 64) {
        #pragma unroll
        for (int r = 0; r < 16; r++) {
            int i = ty * 16 + r;
            h_s[tx][(i + tx) & 63] = h[(size_t)(i0 + i) * F_IN + k0 + tx];
        }
        {
            const float4* Wg = reinterpret_cast<const float4*>(W + (size_t)k0 * F_OUT);
            float4* Ws4 = reinterpret_cast<float4*>(&W_s[0][0]);
            #pragma unroll
            for (int r = 0; r < 8; r++) Ws4[t + r * 256] = Wg[t + r * 256];
        }
        __syncthreads();
        #pragma unroll 8
        for (int k = 0; k < 64; k++) {
            float4 wv = reinterpret_cast<float4*>(&W_s[k][0])[lane];
            #pragma unroll
            for (int r = 0; r < 8; r++) {
                float hv = h_s[k][(ib + r + k) & 63];
                acc[r][0] += hv * wv.x; acc[r][1] += hv * wv.y;
                acc[r][2] += hv * wv.z; acc[r][3] += hv * wv.w;
            }
        }
        __syncthreads();
    }
    #pragma unroll
    for (int r = 0; r < 8; r++) {
        int i = i0 + ib + r;
        reinterpret_cast<float4*>(&g_Wh[(size_t)i * F_OUT])[lane] =
            make_float4(acc[r][0], acc[r][1], acc[r][2], acc[r][3]);
    }
}

// ---------------------------------------------------------------------------
// Kernel A2: x=Wh.a1, y=Wh.a2 -> E, Ep, F, Fp, bf16 compare keys
// ---------------------------------------------------------------------------
__global__ __launch_bounds__(256) void attn_coeffs(const float* __restrict__ a) {
    const int t = threadIdx.x, lane = t & 31, wid = t >> 5;
    const int i = blockIdx.x * 8 + wid;
    float4 wh = reinterpret_cast<const float4*>(&g_Wh[(size_t)i * F_OUT])[lane];
    float4 a1 = reinterpret_cast<const float4*>(a)[lane];
    float4 a2 = reinterpret_cast<const float4*>(a + F_OUT)[lane];
    float s1 = wh.x * a1.x + wh.y * a1.y + wh.z * a1.z + wh.w * a1.w;
    float s2 = wh.x * a2.x + wh.y * a2.y + wh.z * a2.z + wh.w * a2.w;
    #pragma unroll
    for (int o = 16; o > 0; o >>= 1) {
        s1 += __shfl_xor_sync(0xFFFFFFFFu, s1, o);
        s2 += __shfl_xor_sync(0xFFFFFFFFu, s2, o);
    }
    if (lane == 0) {
        g_E[i]  = expf(s1);
        g_Ep[i] = expf(0.2f * s1);
        g_F[i]  = expf(s2);
        g_Fp[i] = expf(0.2f * s2);
        g_ybf[i] = __float2bfloat16(s2);
        __nv_bfloat16 nb = __float2bfloat16(-s1);
        uint32_t b = (uint32_t)*reinterpret_cast<unsigned short*>(&nb);
        g_nx2[i] = b | (b << 16);
    }
}

// ---------------------------------------------------------------------------
// Kernel A3: build B planes [mat][NB n][8192 j] bf16.
// ---------------------------------------------------------------------------
__global__ __launch_bounds__(256) void prep_B() {
    __shared__ float s[F_OUT][65];
    __shared__ float sF[64], sFp[64];
    const int t = threadIdx.x;
    const int j0 = blockIdx.x * 64;

    {
        int f4 = (t & 31) * 4;
        int jr = t >> 5;
        #pragma unroll
        for (int p = 0; p < 8; p++) {
            int j = p * 8 + jr;
            float4 v = reinterpret_cast<const float4*>(&g_Wh[(size_t)(j0 + j) * F_OUT])[t & 31];
            s[f4 + 0][j] = v.x; s[f4 + 1][j] = v.y;
            s[f4 + 2][j] = v.z; s[f4 + 3][j] = v.w;
        }
    }
    if (t < 64) { sF[t] = g_F[j0 + t]; sFp[t] = g_Fp[j0 + t]; }
    __syncthreads();

    const int f = t >> 1, half = t & 1;
    #pragma unroll
    for (int q = 0; q < 4; q++) {
        uint32_t b1h[4], b1l[4], b0h[4], b0l[4];
        #pragma unroll
        for (int k = 0; k < 4; k++) {
            int j = half * 32 + q * 8 + k * 2;
            float w0 = s[f][j], w1 = s[f][j + 1];
            float x0 = sF[j] * w0,  x1 = sF[j + 1] * w1;
            float z0 = sFp[j] * w0, z1 = sFp[j + 1] * w1;
            __nv_bfloat162 h1 = __floats2bfloat162_rn(x0, x1);
            __nv_bfloat162 l1 = __floats2bfloat162_rn(x0 - __bfloat162float(h1.x),
                                                      x1 - __bfloat162float(h1.y));
            __nv_bfloat162 h0 = __floats2bfloat162_rn(z0, z1);
            __nv_bfloat162 l0 = __floats2bfloat162_rn(z0 - __bfloat162float(h0.x),
                                                      z1 - __bfloat162float(h0.y));
            b1h[k] = *reinterpret_cast<uint32_t*>(&h1);
            b1l[k] = *reinterpret_cast<uint32_t*>(&l1);
            b0h[k] = *reinterpret_cast<uint32_t*>(&h0);
            b0l[k] = *reinterpret_cast<uint32_t*>(&l0);
        }
        size_t off = (size_t)f * N_NODES + j0 + half * 32 + q * 8;
        *reinterpret_cast<uint4*>(&g_B[((size_t)0 * NB) * N_NODES + off]) = make_uint4(b1h[0], b1h[1], b1h[2], b1h[3]);
        *reinterpret_cast<uint4*>(&g_B[((size_t)1 * NB) * N_NODES + off]) = make_uint4(b1l[0], b1l[1], b1l[2], b1l[3]);
        *reinterpret_cast<uint4*>(&g_B[((size_t)2 * NB) * N_NODES + off]) = make_uint4(b0h[0], b0h[1], b0h[2], b0h[3]);
        *reinterpret_cast<uint4*>(&g_B[((size_t)3 * NB) * N_NODES + off]) = make_uint4(b0l[0], b0l[1], b0l[2], b0l[3]);
    }

    if (t < 64) {
        int j = j0 + t;
        float Fv = sF[t], Fpv = sFp[t];
        __nv_bfloat16 h1 = __float2bfloat16(Fv);
        __nv_bfloat16 l1 = __float2bfloat16(Fv - __bfloat162float(h1));
        __nv_bfloat16 h0 = __float2bfloat16(Fpv);
        __nv_bfloat16 l0 = __float2bfloat16(Fpv - __bfloat162float(h0));
        g_B[((size_t)0 * NB + 128) * N_NODES + j] = h1;
        g_B[((size_t)1 * NB + 128) * N_NODES + j] = l1;
        g_B[((size_t)2 * NB + 128) * N_NODES + j] = h0;
        g_B[((size_t)3 * NB + 128) * N_NODES + j] = l0;
        __nv_bfloat16 z = __float2bfloat16(0.0f);
        #pragma unroll
        for (int r = 129; r < NB; r++)
            #pragma unroll
            for (int m = 0; m < 4; m++)
                g_B[((size_t)m * NB + r) * N_NODES + j] = z;
    }
}

// ---------------------------------------------------------------------------
// Kernel B: tensor-core mask-GEMM aggregation + fused epilogue.
// 512 threads = 16 warps in a 2(m) x 8(n) grid: wm = wid&1, wn = wid>>1.
// Each warp: 2 m16 tiles (rows wm*32..+32) x 16 n-cols (wn*16..+16).
// B fragments loaded once per (plane, ks) and reused for both m-tiles
// -> B LDSM traffic halves vs the 4x4 grid (smem-BW was the R12 limiter).
// den column (n=128) handled by warps wn=4..7, one plane each; partials
// combined in the epilogue through 1 KB of smem.
// ---------------------------------------------------------------------------
__global__ __launch_bounds__(512, 1) void aggregate(const int* __restrict__ adj,
                                                    float* __restrict__ out) {
    extern __shared__ __align__(1024) char smem[];
    const uint32_t sb = smem_u32(smem);
    // [0, 32768):        A buffers (2 x {M1 8KB, M0 8KB})
    // [32768, 172032):   B buffers (2 x 4 planes x 17408 B)
    // [172032, 173056):  den partials (4 x 64 floats)
    float* den_part = reinterpret_cast<float*>(smem + 172032);

    const int t = threadIdx.x, lane = t & 31, wid = t >> 5;
    const int wm = wid & 1, wn = wid >> 1;       // 2 x 8 warp grid
    const int i0 = blockIdx.x * 64;

    const int i_my = t >> 3;   // 0..63
    const int jq   = t & 7;    // 8-j chunk

    const uint32_t nx2 = g_nx2[i0 + i_my];

    float acc1[2][2][4] = {};   // [m-tile][n8][frag]
    float acc0[2][2][4] = {};
    float accd[2][4]    = {};   // den partial (warps wn>=4)

    // B cp.async issue for one tile into buffer p (4352 16B-chunks, 512 thr)
    auto issue_b = [&](int j0t, int p) {
        const uint32_t BB = sb + 32768 + p * 69632;
        #pragma unroll
        for (int k = 0; k < 8; k++) {
            int c = k * 512 + t;
            int plane = c / 1088;
            int rem = c - plane * 1088;
            int n = rem >> 3, ch = rem & 7;
            const void* src = &g_B[((size_t)plane * NB + n) * N_NODES + j0t + ch * 8];
            uint32_t dst = BB + plane * 17408 + n * 128 + ((ch ^ (n & 7)) << 4);
            cpa16(dst, src);
        }
        if (t < 256) {   // leftover: plane 3 tail
            int rem = 832 + t;
            int n = rem >> 3, ch = rem & 7;
            const void* src = &g_B[((size_t)3 * NB + n) * N_NODES + j0t + ch * 8];
            uint32_t dst = BB + 3 * 17408 + n * 128 + ((ch ^ (n & 7)) << 4);
            cpa16(dst, src);
        }
    };

    // prologue: adj tile 0 prefetch + B tile 0 cp.async
    int4 adjv[2];
    {
        const int4* ap = reinterpret_cast<const int4*>(
            adj + (size_t)(i0 + i_my) * N_NODES + jq * 8);
        adjv[0] = ap[0]; adjv[1] = ap[1];
    }
    issue_b(0, 0);
    CP_COMMIT();

    for (int tl = 0; tl < NTILES; tl++) {
        const int p = tl & 1;
        const int j0 = tl * 64;
        const uint32_t A1 = sb + p * 16384;
        const uint32_t A0 = A1 + 8192;
        const uint32_t BB = sb + 32768 + p * 69632;

        CP_WAIT0();   // this tile's B planes have landed

        // ---- build masks (each thread: 8 j's for one i-row) ----
        {
            const uint32_t* yb = reinterpret_cast<const uint32_t*>(g_ybf + j0 + jq * 8);
            uint32_t m1r[4], m0r[4];
            #pragma unroll
            for (int q = 0; q < 2; q++) {
                int4 av = adjv[q];
                uint32_t y01 = yb[2 * q], y23 = yb[2 * q + 1];
                uint32_t u01 = (uint32_t)av.x | ((uint32_t)av.y << 16);
                uint32_t u23 = (uint32_t)av.z | ((uint32_t)av.w << 16);
                uint32_t a01 = u01 * 0x3F80u, a23 = u23 * 0x3F80u;  // bf16 1.0 per set half
                uint32_t p01 = set_gt_bf2(y01, nx2), p23 = set_gt_bf2(y23, nx2);
                uint32_t q01 = mul_bf2(a01, p01), q23 = mul_bf2(a23, p23);
                m1r[2 * q] = q01;               m1r[2 * q + 1] = q23;
                m0r[2 * q] = sub_bf2(a01, q01); m0r[2 * q + 1] = sub_bf2(a23, q23);
            }
            uint32_t rowb = (uint32_t)i_my * 128;
            uint32_t so = (uint32_t)((jq ^ (i_my & 7)) << 4);
            sts128(A1 + rowb + so, make_uint4(m1r[0], m1r[1], m1r[2], m1r[3]));
            sts128(A0 + rowb + so, make_uint4(m0r[0], m0r[1], m0r[2], m0r[3]));
        }
        __syncthreads();

        // ---- prefetch next tile (overlaps compute below) ----
        if (tl + 1 < NTILES) {
            const int jn = j0 + 64;
            const int4* ap = reinterpret_cast<const int4*>(
                adj + (size_t)(i0 + i_my) * N_NODES + jn + jq * 8);
            adjv[0] = ap[0]; adjv[1] = ap[1];
            issue_b(jn, (tl + 1) & 1);
        }
        CP_COMMIT();

        // ---- compute: 4 k-steps; B fragments shared across both m-tiles ----
        #pragma unroll
        for (int ks = 0; ks < 4; ks++) {
            uint32_t am1[2][4], am0[2][4];
            #pragma unroll
            for (int mt = 0; mt < 2; mt++) {
                uint32_t arow = (uint32_t)(wm * 32 + mt * 16
                                           + (lane & 7) + ((lane >> 3) & 1) * 8);
                uint32_t ach = (uint32_t)(ks * 2 + (lane >> 4));
                uint32_t aoff = arow * 128 + ((ach ^ (arow & 7)) << 4);
                ldm4(am1[mt], A1 + aoff);
                ldm4(am0[mt], A0 + aoff);
            }

            uint32_t nrow = (uint32_t)(wn * 2 + (lane >> 4)) * 8 + (lane & 7);
            uint32_t bch = (uint32_t)(ks * 2 + ((lane >> 3) & 1));
            uint32_t boff = nrow * 128 + ((bch ^ (nrow & 7)) << 4);
            uint32_t b1h[4], b1l[4], b0h[4], b0l[4];
            ldm4(b1h, BB + 0 * 17408 + boff);
            ldm4(b1l, BB + 1 * 17408 + boff);
            ldm4(b0h, BB + 2 * 17408 + boff);
            ldm4(b0l, BB + 3 * 17408 + boff);

            #pragma unroll
            for (int mt = 0; mt < 2; mt++) {
                #pragma unroll
                for (int ns = 0; ns < 2; ns++) {
                    hmma(acc1[mt][ns], am1[mt], b1h + 2 * ns);
                    hmma(acc1[mt][ns], am1[mt], b1l + 2 * ns);
                    hmma(acc0[mt][ns], am0[mt], b0h + 2 * ns);
                    hmma(acc0[mt][ns], am0[mt], b0l + 2 * ns);
                }
            }

            // den column: warp wn = 4+pl owns plane pl
            if (wn >= 4) {
                int pl = wn - 4;
                uint32_t dnrow = 128 + (lane & 7);
                uint32_t daddr = BB + pl * 17408 + dnrow * 128
                               + ((bch ^ (dnrow & 7)) << 4);
                uint32_t bd[2]; ldm2(bd, daddr);
                if (pl < 2) { hmma(accd[0], am1[0], bd); hmma(accd[1], am1[1], bd); }
                else        { hmma(accd[0], am0[0], bd); hmma(accd[1], am0[1], bd); }
            }
        }
    }

    // ---- den partials -> smem ----
    if (wn >= 4 && (lane & 3) == 0) {
        int pl = wn - 4;
        #pragma unroll
        for (int mt = 0; mt < 2; mt++) {
            int r = wm * 32 + mt * 16 + (lane >> 2);
            den_part[pl * 64 + r]     = accd[mt][0];
            den_part[pl * 64 + r + 8] = accd[mt][2];
        }
    }
    __syncthreads();

    // ---- epilogue: combine dens, scale, normalize, ELU, store ----
    #pragma unroll
    for (int mt = 0; mt < 2; mt++) {
        int rA = wm * 32 + mt * 16 + (lane >> 2);
        int rB = rA + 8;
        float EA = g_E[i0 + rA], EpA = g_Ep[i0 + rA];
        float EB = g_E[i0 + rB], EpB = g_Ep[i0 + rB];
        float dA = EA * (den_part[rA] + den_part[64 + rA])
                 + EpA * (den_part[128 + rA] + den_part[192 + rA]);
        float dB = EB * (den_part[rB] + den_part[64 + rB])
                 + EpB * (den_part[128 + rB] + den_part[192 + rB]);
        float iA = 1.0f / dA, iB = 1.0f / dB;

        #pragma unroll
        for (int ns = 0; ns < 2; ns++) {
            int n = wn * 16 + ns * 8 + (lane & 3) * 2;
            float v00 = (EA * acc1[mt][ns][0] + EpA * acc0[mt][ns][0]) * iA;
            float v01 = (EA * acc1[mt][ns][1] + EpA * acc0[mt][ns][1]) * iA;
            float v10 = (EB * acc1[mt][ns][2] + EpB * acc0[mt][ns][2]) * iB;
            float v11 = (EB * acc1[mt][ns][3] + EpB * acc0[mt][ns][3]) * iB;
            v00 = (v00 > 0.0f) ? v00 : expm1f(v00);
            v01 = (v01 > 0.0f) ? v01 : expm1f(v01);
            v10 = (v10 > 0.0f) ? v10 : expm1f(v10);
            v11 = (v11 > 0.0f) ? v11 : expm1f(v11);
            *reinterpret_cast<float2*>(&out[(size_t)(i0 + rA) * F_OUT + n]) = make_float2(v00, v01);
            *reinterpret_cast<float2*>(&out[(size_t)(i0 + rB) * F_OUT + n]) = make_float2(v10, v11);
        }
    }
}

// ---------------------------------------------------------------------------
extern "C" void kernel_launch(void* const* d_in, const int* in_sizes, int n_in,
                              void* d_out, int out_size) {
    const float* h   = (const float*)d_in[0];
    const int*   adj = (const int*)d_in[1];
    const float* W   = (const float*)d_in[2];
    const float* a   = (const float*)d_in[3];
    float* out = (float*)d_out;

    const int AGG_SMEM = 173056;
    cudaFuncSetAttribute(aggregate, cudaFuncAttributeMaxDynamicSharedMemorySize, AGG_SMEM);

    gemm_wh<<<N_NODES / 64, 256>>>(h, W);
    attn_coeffs<<<N_NODES / 8, 256>>>(a);
    prep_B<<<N_NODES / 64, 256>>>();
    aggregate<<<N_NODES / 64, 512, AGG_SMEM>>>(adj, out);
}

// round 14
// speedup vs baseline: 4.7542x; 1.3300x over previous
#include <cuda_runtime.h>
#include <cuda_bf16.h>
#include <cuda_fp16.h>
#include <cstdint>
#include <math.h>

#define N_NODES 8192
#define F_IN    256
#define F_OUT   128
#define NB      136            // GEMM N: 128 feats + den col(128) + 7 zero pad
#define NTILES  (N_NODES / 64) // 128 k-tiles of 64

// ------------------------------ device scratch ------------------------------
__device__ float    g_Wh[N_NODES * F_OUT];        // 4 MB
__device__ float    g_E[N_NODES], g_Ep[N_NODES];  // e^x, e^{0.2x}
__device__ float    g_F[N_NODES], g_Fp[N_NODES];  // e^y, e^{0.2y}
__device__ __half   g_yhf[N_NODES];               // fp16(y_j)
__device__ uint32_t g_nx2[N_NODES];               // {fp16(-x_i)} x2
// B planes [pl][NB][8192] fp16; pl: 0 = B1 = F*Wh, 1 = B0 = Fp*Wh
__device__ __half   g_B[2 * NB * N_NODES];        // 4.5 MB

// ------------------------------ asm helpers ---------------------------------
__device__ __forceinline__ uint32_t smem_u32(const void* p) {
    uint32_t a;
    asm("{ .reg .u64 t; cvta.to.shared.u64 t, %1; cvt.u32.u64 %0, t; }"
        : "=r"(a) : "l"(p));
    return a;
}
__device__ __forceinline__ void sts128(uint32_t addr, uint4 v) {
    asm volatile("st.shared.v4.b32 [%0], {%1,%2,%3,%4};"
                 :: "r"(addr), "r"(v.x), "r"(v.y), "r"(v.z), "r"(v.w) : "memory");
}
__device__ __forceinline__ uint32_t set_gt_h2(uint32_t a, uint32_t b) {
    uint32_t d;
    asm("set.gt.f16x2.f16x2 %0, %1, %2;" : "=r"(d) : "r"(a), "r"(b));
    return d;
}
__device__ __forceinline__ uint32_t mul_h2(uint32_t a, uint32_t b) {
    uint32_t d;
    asm("mul.rn.f16x2 %0, %1, %2;" : "=r"(d) : "r"(a), "r"(b));
    return d;
}
__device__ __forceinline__ uint32_t sub_h2(uint32_t a, uint32_t b) {
    uint32_t d;
    asm("sub.rn.f16x2 %0, %1, %2;" : "=r"(d) : "r"(a), "r"(b));
    return d;
}
__device__ __forceinline__ void ldm4(uint32_t* r, uint32_t addr) {
    asm volatile("ldmatrix.sync.aligned.m8n8.x4.shared.b16 {%0,%1,%2,%3}, [%4];"
                 : "=r"(r[0]), "=r"(r[1]), "=r"(r[2]), "=r"(r[3]) : "r"(addr));
}
__device__ __forceinline__ void ldm2(uint32_t* r, uint32_t addr) {
    asm volatile("ldmatrix.sync.aligned.m8n8.x2.shared.b16 {%0,%1}, [%2];"
                 : "=r"(r[0]), "=r"(r[1]) : "r"(addr));
}
__device__ __forceinline__ void hmma(float* c, const uint32_t* a, const uint32_t* b) {
    asm volatile("mma.sync.aligned.m16n8k16.row.col.f32.f16.f16.f32 "
                 "{%0,%1,%2,%3}, {%4,%5,%6,%7}, {%8,%9}, {%0,%1,%2,%3};"
                 : "+f"(c[0]), "+f"(c[1]), "+f"(c[2]), "+f"(c[3])
                 : "r"(a[0]), "r"(a[1]), "r"(a[2]), "r"(a[3]),
                   "r"(b[0]), "r"(b[1]));
}
__device__ __forceinline__ void cpa16(uint32_t dst, const void* src) {
    asm volatile("cp.async.cg.shared.global [%0], [%1], 16;"
                 :: "r"(dst), "l"(src) : "memory");
}
#define CP_COMMIT() asm volatile("cp.async.commit_group;" ::: "memory")
#define CP_WAIT0()  asm volatile("cp.async.wait_group 0;" ::: "memory")

// ---------------------------------------------------------------------------
// Kernel A: Wh = h @ W   (known-good)
// ---------------------------------------------------------------------------
__global__ __launch_bounds__(256) void gemm_wh(const float* __restrict__ h,
                                               const float* __restrict__ W) {
    __shared__ __align__(16) float h_s[64][64];
    __shared__ __align__(16) float W_s[64][F_OUT];

    const int t = threadIdx.x, lane = t & 31, wid = t >> 5;
    const int ib = wid * 8, i0 = blockIdx.x * 64;
    const int tx = t & 63, ty = t >> 6;

    float acc[8][4] = {};
    for (int k0 = 0; k0 < F_IN; k0 += 64) {
        #pragma unroll
        for (int r = 0; r < 16; r++) {
            int i = ty * 16 + r;
            h_s[tx][(i + tx) & 63] = h[(size_t)(i0 + i) * F_IN + k0 + tx];
        }
        {
            const float4* Wg = reinterpret_cast<const float4*>(W + (size_t)k0 * F_OUT);
            float4* Ws4 = reinterpret_cast<float4*>(&W_s[0][0]);
            #pragma unroll
            for (int r = 0; r < 8; r++) Ws4[t + r * 256] = Wg[t + r * 256];
        }
        __syncthreads();
        #pragma unroll 8
        for (int k = 0; k < 64; k++) {
            float4 wv = reinterpret_cast<float4*>(&W_s[k][0])[lane];
            #pragma unroll
            for (int r = 0; r < 8; r++) {
                float hv = h_s[k][(ib + r + k) & 63];
                acc[r][0] += hv * wv.x; acc[r][1] += hv * wv.y;
                acc[r][2] += hv * wv.z; acc[r][3] += hv * wv.w;
            }
        }
        __syncthreads();
    }
    #pragma unroll
    for (int r = 0; r < 8; r++) {
        int i = i0 + ib + r;
        reinterpret_cast<float4*>(&g_Wh[(size_t)i * F_OUT])[lane] =
            make_float4(acc[r][0], acc[r][1], acc[r][2], acc[r][3]);
    }
}

// ---------------------------------------------------------------------------
// Kernel A2: x=Wh.a1, y=Wh.a2 -> E, Ep, F, Fp, fp16 compare keys
// ---------------------------------------------------------------------------
__global__ __launch_bounds__(256) void attn_coeffs(const float* __restrict__ a) {
    const int t = threadIdx.x, lane = t & 31, wid = t >> 5;
    const int i = blockIdx.x * 8 + wid;
    float4 wh = reinterpret_cast<const float4*>(&g_Wh[(size_t)i * F_OUT])[lane];
    float4 a1 = reinterpret_cast<const float4*>(a)[lane];
    float4 a2 = reinterpret_cast<const float4*>(a + F_OUT)[lane];
    float s1 = wh.x * a1.x + wh.y * a1.y + wh.z * a1.z + wh.w * a1.w;
    float s2 = wh.x * a2.x + wh.y * a2.y + wh.z * a2.z + wh.w * a2.w;
    #pragma unroll
    for (int o = 16; o > 0; o >>= 1) {
        s1 += __shfl_xor_sync(0xFFFFFFFFu, s1, o);
        s2 += __shfl_xor_sync(0xFFFFFFFFu, s2, o);
    }
    if (lane == 0) {
        g_E[i]  = expf(s1);
        g_Ep[i] = expf(0.2f * s1);
        g_F[i]  = expf(s2);
        g_Fp[i] = expf(0.2f * s2);
        g_yhf[i] = __float2half(s2);
        __half nh = __float2half(-s1);
        uint32_t b = (uint32_t)*reinterpret_cast<unsigned short*>(&nh);
        g_nx2[i] = b | (b << 16);
    }
}

// ---------------------------------------------------------------------------
// Kernel A3: build B planes [pl][NB n][8192 j] fp16.
//   n<128:  pl0 = F_j*Wh[j][n], pl1 = Fp_j*Wh[j][n]
//   n=128:  pl0 = F_j, pl1 = Fp_j   (denominator column)
//   n=129..135: zero
// ---------------------------------------------------------------------------
__global__ __launch_bounds__(256) void prep_B() {
    __shared__ float s[F_OUT][65];
    __shared__ float sF[64], sFp[64];
    const int t = threadIdx.x;
    const int j0 = blockIdx.x * 64;

    {
        int f4 = (t & 31) * 4;
        int jr = t >> 5;
        #pragma unroll
        for (int p = 0; p < 8; p++) {
            int j = p * 8 + jr;
            float4 v = reinterpret_cast<const float4*>(&g_Wh[(size_t)(j0 + j) * F_OUT])[t & 31];
            s[f4 + 0][j] = v.x; s[f4 + 1][j] = v.y;
            s[f4 + 2][j] = v.z; s[f4 + 3][j] = v.w;
        }
    }
    if (t < 64) { sF[t] = g_F[j0 + t]; sFp[t] = g_Fp[j0 + t]; }
    __syncthreads();

    const int f = t >> 1, half = t & 1;
    #pragma unroll
    for (int q = 0; q < 4; q++) {
        uint32_t b1[4], b0[4];
        #pragma unroll
        for (int k = 0; k < 4; k++) {
            int j = half * 32 + q * 8 + k * 2;
            float w0 = s[f][j], w1 = s[f][j + 1];
            __half2 h1 = __floats2half2_rn(sF[j] * w0,  sF[j + 1] * w1);
            __half2 h0 = __floats2half2_rn(sFp[j] * w0, sFp[j + 1] * w1);
            b1[k] = *reinterpret_cast<uint32_t*>(&h1);
            b0[k] = *reinterpret_cast<uint32_t*>(&h0);
        }
        size_t off = (size_t)f * N_NODES + j0 + half * 32 + q * 8;
        *reinterpret_cast<uint4*>(&g_B[off])                          = make_uint4(b1[0], b1[1], b1[2], b1[3]);
        *reinterpret_cast<uint4*>(&g_B[(size_t)NB * N_NODES + off])   = make_uint4(b0[0], b0[1], b0[2], b0[3]);
    }

    if (t < 64) {
        int j = j0 + t;
        g_B[(size_t)128 * N_NODES + j]                        = __float2half(sF[t]);
        g_B[((size_t)NB + 128) * N_NODES + j]                 = __float2half(sFp[t]);
        __half z = __float2half(0.0f);
        #pragma unroll
        for (int r = 129; r < NB; r++) {
            g_B[(size_t)r * N_NODES + j] = z;
            g_B[((size_t)NB + r) * N_NODES + j] = z;
        }
    }
}

// ---------------------------------------------------------------------------
// Kernel B: fp16 single-plane mask-GEMM aggregation + fused epilogue.
// 512 threads = 16 warps, 2(m) x 8(n): wm = wid&1, wn = wid>>1.
// acc1 += M1 @ B1, acc0 += M0 @ B0 (fp32 accum; masks exact fp16 0/1).
// den column n=128: warp wn==6 does plane0 (M1*F), wn==7 plane1 (M0*Fp).
// ---------------------------------------------------------------------------
__global__ __launch_bounds__(512, 1) void aggregate(const int* __restrict__ adj,
                                                    float* __restrict__ out) {
    extern __shared__ __align__(1024) char smem[];
    const uint32_t sb = smem_u32(smem);
    // [0, 32768):        A buffers (2 x {M1 8KB, M0 8KB})
    // [32768, 102400):   B buffers (2 x 2 planes x 17408 B)
    // [102400, 102912):  den partials (2 x 64 floats)
    float* den_part = reinterpret_cast<float*>(smem + 102400);

    const int t = threadIdx.x, lane = t & 31, wid = t >> 5;
    const int wm = wid & 1, wn = wid >> 1;       // 2 x 8 warp grid
    const int i0 = blockIdx.x * 64;

    const int i_my = t >> 3;   // 0..63
    const int jq   = t & 7;    // 8-j chunk

    const uint32_t nx2 = g_nx2[i0 + i_my];

    float acc1[2][2][4] = {};   // [m-tile][n8][frag]
    float acc0[2][2][4] = {};
    float accd[2][4]    = {};   // den partial (warps wn==6,7)

    // B cp.async issue for one tile into buffer p (2176 16B-chunks, 512 thr)
    auto issue_b = [&](int j0t, int p) {
        const uint32_t BB = sb + 32768 + p * 34816;
        #pragma unroll
        for (int k = 0; k < 4; k++) {
            int c = k * 512 + t;
            int plane = c / 1088;
            int rem = c - plane * 1088;
            int n = rem >> 3, ch = rem & 7;
            const void* src = &g_B[((size_t)plane * NB + n) * N_NODES + j0t + ch * 8];
            uint32_t dst = BB + plane * 17408 + n * 128 + ((ch ^ (n & 7)) << 4);
            cpa16(dst, src);
        }
        if (t < 128) {   // leftover: plane 1 tail (rem 960..1087)
            int rem = 960 + t;
            int n = rem >> 3, ch = rem & 7;
            const void* src = &g_B[((size_t)NB + n) * N_NODES + j0t + ch * 8];
            uint32_t dst = BB + 17408 + n * 128 + ((ch ^ (n & 7)) << 4);
            cpa16(dst, src);
        }
    };

    // prologue: adj tile 0 prefetch + B tile 0 cp.async
    int4 adjv[2];
    {
        const int4* ap = reinterpret_cast<const int4*>(
            adj + (size_t)(i0 + i_my) * N_NODES + jq * 8);
        adjv[0] = ap[0]; adjv[1] = ap[1];
    }
    issue_b(0, 0);
    CP_COMMIT();

    for (int tl = 0; tl < NTILES; tl++) {
        const int p = tl & 1;
        const int j0 = tl * 64;
        const uint32_t A1 = sb + p * 16384;
        const uint32_t A0 = A1 + 8192;
        const uint32_t BB = sb + 32768 + p * 34816;

        CP_WAIT0();   // this tile's B planes have landed

        // ---- build masks (each thread: 8 j's for one i-row) ----
        {
            const uint32_t* yb = reinterpret_cast<const uint32_t*>(g_yhf + j0 + jq * 8);
            uint32_t m1r[4], m0r[4];
            #pragma unroll
            for (int q = 0; q < 2; q++) {
                int4 av = adjv[q];
                uint32_t y01 = yb[2 * q], y23 = yb[2 * q + 1];
                uint32_t u01 = (uint32_t)av.x | ((uint32_t)av.y << 16);
                uint32_t u23 = (uint32_t)av.z | ((uint32_t)av.w << 16);
                uint32_t a01 = u01 * 0x3C00u, a23 = u23 * 0x3C00u;  // fp16 1.0 per set half
                uint32_t p01 = set_gt_h2(y01, nx2), p23 = set_gt_h2(y23, nx2);
                uint32_t q01 = mul_h2(a01, p01), q23 = mul_h2(a23, p23);
                m1r[2 * q] = q01;              m1r[2 * q + 1] = q23;
                m0r[2 * q] = sub_h2(a01, q01); m0r[2 * q + 1] = sub_h2(a23, q23);
            }
            uint32_t rowb = (uint32_t)i_my * 128;
            uint32_t so = (uint32_t)((jq ^ (i_my & 7)) << 4);
            sts128(A1 + rowb + so, make_uint4(m1r[0], m1r[1], m1r[2], m1r[3]));
            sts128(A0 + rowb + so, make_uint4(m0r[0], m0r[1], m0r[2], m0r[3]));
        }
        __syncthreads();

        // ---- prefetch next tile (overlaps compute below) ----
        if (tl + 1 < NTILES) {
            const int jn = j0 + 64;
            const int4* ap = reinterpret_cast<const int4*>(
                adj + (size_t)(i0 + i_my) * N_NODES + jn + jq * 8);
            adjv[0] = ap[0]; adjv[1] = ap[1];
            issue_b(jn, (tl + 1) & 1);
        }
        CP_COMMIT();

        // ---- compute: 4 k-steps; B fragments shared across both m-tiles ----
        #pragma unroll
        for (int ks = 0; ks < 4; ks++) {
            uint32_t am1[2][4], am0[2][4];
            #pragma unroll
            for (int mt = 0; mt < 2; mt++) {
                uint32_t arow = (uint32_t)(wm * 32 + mt * 16
                                           + (lane & 7) + ((lane >> 3) & 1) * 8);
                uint32_t ach = (uint32_t)(ks * 2 + (lane >> 4));
                uint32_t aoff = arow * 128 + ((ach ^ (arow & 7)) << 4);
                ldm4(am1[mt], A1 + aoff);
                ldm4(am0[mt], A0 + aoff);
            }

            uint32_t nrow = (uint32_t)(wn * 2 + (lane >> 4)) * 8 + (lane & 7);
            uint32_t bch = (uint32_t)(ks * 2 + ((lane >> 3) & 1));
            uint32_t boff = nrow * 128 + ((bch ^ (nrow & 7)) << 4);
            uint32_t b1f[4], b0f[4];
            ldm4(b1f, BB + boff);
            ldm4(b0f, BB + 17408 + boff);

            #pragma unroll
            for (int mt = 0; mt < 2; mt++) {
                #pragma unroll
                for (int ns = 0; ns < 2; ns++) {
                    hmma(acc1[mt][ns], am1[mt], b1f + 2 * ns);
                    hmma(acc0[mt][ns], am0[mt], b0f + 2 * ns);
                }
            }

            // den column: wn==6 -> plane0 (M1), wn==7 -> plane1 (M0)
            if (wn >= 6) {
                int pl = wn - 6;
                uint32_t dnrow = 128 + (lane & 7);
                uint32_t daddr = BB + pl * 17408 + dnrow * 128
                               + ((bch ^ (dnrow & 7)) << 4);
                uint32_t bd[2]; ldm2(bd, daddr);
                if (pl == 0) { hmma(accd[0], am1[0], bd); hmma(accd[1], am1[1], bd); }
                else         { hmma(accd[0], am0[0], bd); hmma(accd[1], am0[1], bd); }
            }
        }
    }

    // ---- den partials -> smem ----
    if (wn >= 6 && (lane & 3) == 0) {
        int pl = wn - 6;
        #pragma unroll
        for (int mt = 0; mt < 2; mt++) {
            int r = wm * 32 + mt * 16 + (lane >> 2);
            den_part[pl * 64 + r]     = accd[mt][0];
            den_part[pl * 64 + r + 8] = accd[mt][2];
        }
    }
    __syncthreads();

    // ---- epilogue: combine dens, scale, normalize, ELU, store ----
    #pragma unroll
    for (int mt = 0; mt < 2; mt++) {
        int rA = wm * 32 + mt * 16 + (lane >> 2);
        int rB = rA + 8;
        float EA = g_E[i0 + rA], EpA = g_Ep[i0 + rA];
        float EB = g_E[i0 + rB], EpB = g_Ep[i0 + rB];
        float dA = EA * den_part[rA] + EpA * den_part[64 + rA];
        float dB = EB * den_part[rB] + EpB * den_part[64 + rB];
        float iA = 1.0f / dA, iB = 1.0f / dB;

        #pragma unroll
        for (int ns = 0; ns < 2; ns++) {
            int n = wn * 16 + ns * 8 + (lane & 3) * 2;
            float v00 = (EA * acc1[mt][ns][0] + EpA * acc0[mt][ns][0]) * iA;
            float v01 = (EA * acc1[mt][ns][1] + EpA * acc0[mt][ns][1]) * iA;
            float v10 = (EB * acc1[mt][ns][2] + EpB * acc0[mt][ns][2]) * iB;
            float v11 = (EB * acc1[mt][ns][3] + EpB * acc0[mt][ns][3]) * iB;
            v00 = (v00 > 0.0f) ? v00 : expm1f(v00);
            v01 = (v01 > 0.0f) ? v01 : expm1f(v01);
            v10 = (v10 > 0.0f) ? v10 : expm1f(v10);
            v11 = (v11 > 0.0f) ? v11 : expm1f(v11);
            *reinterpret_cast<float2*>(&out[(size_t)(i0 + rA) * F_OUT + n]) = make_float2(v00, v01);
            *reinterpret_cast<float2*>(&out[(size_t)(i0 + rB) * F_OUT + n]) = make_float2(v10, v11);
        }
    }
}

// ---------------------------------------------------------------------------
extern "C" void kernel_launch(void* const* d_in, const int* in_sizes, int n_in,
                              void* d_out, int out_size) {
    const float* h   = (const float*)d_in[0];
    const int*   adj = (const int*)d_in[1];
    const float* W   = (const float*)d_in[2];
    const float* a   = (const float*)d_in[3];
    float* out = (float*)d_out;

    const int AGG_SMEM = 103424;
    cudaFuncSetAttribute(aggregate, cudaFuncAttributeMaxDynamicSharedMemorySize, AGG_SMEM);

    gemm_wh<<<N_NODES / 64, 256>>>(h, W);
    attn_coeffs<<<N_NODES / 8, 256>>>(a);
    prep_B<<<N_NODES / 64, 256>>>();
    aggregate<<<N_NODES / 64, 512, AGG_SMEM>>>(adj, out);
}